// round 9
// baseline (speedup 1.0000x reference)
#include <cuda_runtime.h>
#include <math.h>
#include <stdint.h>

// ---------------- problem constants ----------------
#define TT 2048
#define HH 1024
#define EE 8
#define FF 3584
#define TOPK 2
#define NPAIR (TT * TOPK)
#define BK 32                 // K floats per chunk
#define NS 3                  // pipeline stages
#define ROWF 36               // A smem row stride (floats)
#define ROWB 144              // A smem row stride (bytes)
#define ASTG (128 * ROWB)     // 18432 B A tile
#define BLANE 272             // B smem lane-block stride (bytes): 256 data + 16 pad
#define BHALF (32 * BLANE)    // 8704 B per 64-row B half
#define BSTG (2 * BHALF)      // 17408 B B tile
#define STG (ASTG + BSTG)     // 35840 B per stage
#define STGW (STG / 4)
#define SMEM_DYN (NS * STG)   // 107520 B

// ---------------- device scratch (static; no allocation) ----------------
__device__ int   g_topk_idx[TT][TOPK];
__device__ float g_topk_w[TT][TOPK];
__device__ int   g_counts[EE];
__device__ int   g_offsets[EE];
__device__ int   g_pair_token[NPAIR];
__device__ float g_pair_w[NPAIR];
__device__ float g_xs[(size_t)TT * HH];          // x, tf32-rounded
__device__ float g_act[(size_t)NPAIR * FF];      // activations, tf32-rounded
// frag-major tf32 weights: [e][ftile56][ktile32][mat2][lane32][64]
__device__ float g_w13[58720256];
// frag-major tf32 w2: [e][htile8][ktile112][half2][lane32][64]
__device__ float g_w2c[29360128];

// ---------------- helpers ----------------
__device__ __forceinline__ uint32_t smem_u32(const void* p) {
    uint32_t a;
    asm("{ .reg .u64 t; cvta.to.shared.u64 t, %1; cvt.u32.u64 %0, t; }" : "=r"(a) : "l"(p));
    return a;
}
#define CP16(dst_u32, src_ptr) \
    asm volatile("cp.async.cg.shared.global [%0], [%1], 16;" :: "r"(dst_u32), "l"(src_ptr) : "memory")
#define CP_COMMIT() asm volatile("cp.async.commit_group;" ::: "memory")
#define CP_WAIT(n)  asm volatile("cp.async.wait_group %0;" :: "n"(n) : "memory")

__device__ __forceinline__ unsigned tf32r(float v) {
    unsigned r;
    asm("cvt.rna.tf32.f32 %0, %1;" : "=r"(r) : "f"(v));
    return r;
}
__device__ __forceinline__ void mma1688(float* c, const unsigned* a, unsigned b0, unsigned b1) {
    asm volatile(
        "mma.sync.aligned.m16n8k8.row.col.f32.tf32.tf32.f32 "
        "{%0,%1,%2,%3}, {%4,%5,%6,%7}, {%8,%9}, {%0,%1,%2,%3};"
        : "+f"(c[0]), "+f"(c[1]), "+f"(c[2]), "+f"(c[3])
        : "r"(a[0]), "r"(a[1]), "r"(a[2]), "r"(a[3]), "r"(b0), "r"(b1));
}

// ---------------- small kernels ----------------
__global__ void zero_kernel(float* __restrict__ out, int n) {
    int i = blockIdx.x * blockDim.x + threadIdx.x;
    if (i < n) out[i] = 0.0f;
}
__global__ void conv_x_kernel(const float* __restrict__ x) {
    int i = blockIdx.x * blockDim.x + threadIdx.x;
    if (i < TT * HH) g_xs[i] = __uint_as_float(tf32r(x[i]));
}
// w1/w3 -> frag-major tf32. grid (kt=32, ft=56, e=8), block 512.
__global__ void conv_w13_kernel(const float* __restrict__ w1, const float* __restrict__ w3) {
    int kt = blockIdx.x, ft = blockIdx.y, e = blockIdx.z;
    int tid = threadIdx.x;
    int mat  = tid >> 8;          // 0 = w1, 1 = w3
    int lane = (tid >> 3) & 31;
    int nt   = tid & 7;
    int r4 = lane >> 2, qk = lane & 3;
    const float* src = (mat ? w3 : w1)
        + ((size_t)e * FF + ft * 64 + nt * 8 + r4) * HH + kt * 32 + qk;
    float* dst = g_w13 + (((size_t)e * 56 + ft) * 32 + kt) * 4096
               + mat * 2048 + lane * 64 + nt * 8;
#pragma unroll
    for (int ko = 0; ko < 4; ko++) {
        dst[ko * 2 + 0] = __uint_as_float(tf32r(src[ko * 8]));
        dst[ko * 2 + 1] = __uint_as_float(tf32r(src[ko * 8 + 4]));
    }
}
// w2 -> frag-major tf32. grid (kt=112, ht=8, e=8), block 512.
__global__ void conv_w2_kernel(const float* __restrict__ w2) {
    int kt = blockIdx.x, ht = blockIdx.y, e = blockIdx.z;
    int tid = threadIdx.x;
    int half = tid >> 8;
    int lane = (tid >> 3) & 31;
    int nt   = tid & 7;
    int r4 = lane >> 2, qk = lane & 3;
    const float* src = w2
        + ((size_t)e * HH + ht * 128 + half * 64 + nt * 8 + r4) * FF + kt * 32 + qk;
    float* dst = g_w2c + (((size_t)e * 8 + ht) * 112 + kt) * 4096
               + half * 2048 + lane * 64 + nt * 8;
#pragma unroll
    for (int ko = 0; ko < 4; ko++) {
        dst[ko * 2 + 0] = __uint_as_float(tf32r(src[ko * 8]));
        dst[ko * 2 + 1] = __uint_as_float(tf32r(src[ko * 8 + 4]));
    }
}
__global__ void router_kernel(const float* __restrict__ x, const float* __restrict__ gw) {
    int warp = (blockIdx.x * blockDim.x + threadIdx.x) >> 5;
    int lane = threadIdx.x & 31;
    if (warp >= TT) return;
    const float* xr = x + (size_t)warp * HH;
    float logit[EE];
#pragma unroll
    for (int e = 0; e < EE; e++) {
        const float* g = gw + (size_t)e * HH;
        float s = 0.0f;
        for (int i = lane; i < HH; i += 32) s += xr[i] * g[i];
#pragma unroll
        for (int o = 16; o > 0; o >>= 1) s += __shfl_xor_sync(0xffffffffu, s, o);
        logit[e] = s;
    }
    if (lane == 0) {
        int i0 = 0;
#pragma unroll
        for (int e = 1; e < EE; e++) if (logit[e] > logit[i0]) i0 = e;
        int i1 = (i0 == 0) ? 1 : 0;
#pragma unroll
        for (int e = 0; e < EE; e++) {
            if (e == i0) continue;
            if (logit[e] > logit[i1]) i1 = e;
        }
        float d = logit[i1] - logit[i0];
        float z = expf(d);
        float w0 = 1.0f / (1.0f + z);
        g_topk_idx[warp][0] = i0;
        g_topk_idx[warp][1] = i1;
        g_topk_w[warp][0] = w0;
        g_topk_w[warp][1] = z * w0;
    }
}
__global__ void build_kernel() {
    __shared__ int s_cnt[EE];
    __shared__ int s_cur[EE];
    int tid = threadIdx.x;
    if (tid < EE) s_cnt[tid] = 0;
    __syncthreads();
    for (int p = tid; p < NPAIR; p += blockDim.x)
        atomicAdd(&s_cnt[g_topk_idx[p >> 1][p & 1]], 1);
    __syncthreads();
    if (tid == 0) {
        int off = 0;
        for (int e = 0; e < EE; e++) {
            g_offsets[e] = off;
            g_counts[e]  = s_cnt[e];
            s_cur[e]     = off;
            off += s_cnt[e];
        }
    }
    __syncthreads();
    for (int p = tid; p < NPAIR; p += blockDim.x) {
        int t = p >> 1, k = p & 1;
        int e = g_topk_idx[t][k];
        int slot = atomicAdd(&s_cur[e], 1);
        g_pair_token[slot] = t;
        g_pair_w[slot]     = g_topk_w[t][k];
    }
}

// ======================= GEMM1: act = silu(x@w1^T) * (x@w3^T) =======================
__global__ __launch_bounds__(256)
void gemm1_kernel() {
    extern __shared__ float dsm[];
    __shared__ int s_tok[128];

    int e    = blockIdx.z;
    int n_e  = g_counts[e];
    int row0 = blockIdx.y * 128;
    if (row0 >= n_e) return;
    int bf   = blockIdx.x;           // ftile
    int f0   = bf * 64;
    int base = g_offsets[e];
    int tid  = threadIdx.x;

    if (tid < 128) {
        int r = row0 + tid;
        s_tok[tid] = (r < n_e) ? g_pair_token[base + r] : 0;
    }
    __syncthreads();

    // cp.async descriptors: 4 A + 4 B 16B-chunks per thread
    const char* srcA[4];
    const char* srcB[4];
    int dofA[4], dofB[4];
    const char* wb = (const char*)(g_w13 + (((size_t)e * 56 + bf) * 32) * 4096);
#pragma unroll
    for (int i = 0; i < 4; i++) {
        int idx = tid + 256 * i;
        int row = idx >> 3, c = idx & 7;
        srcA[i] = (const char*)(g_xs + (size_t)s_tok[row] * HH) + c * 16;
        dofA[i] = row * ROWB + c * 16;
        int mat = idx >> 9, bl = (idx >> 4) & 31, o = idx & 15;
        srcB[i] = wb + idx * 16;
        dofB[i] = ASTG + mat * BHALF + bl * BLANE + o * 16;
    }
    uint32_t sb0 = smem_u32(dsm);
    auto issue = [&](int s) {
        uint32_t sg = sb0 + s * STG;
#pragma unroll
        for (int i = 0; i < 4; i++) { CP16(sg + dofA[i], srcA[i]); srcA[i] += 128; }
#pragma unroll
        for (int i = 0; i < 4; i++) { CP16(sg + dofB[i], srcB[i]); srcB[i] += 16384; }
        CP_COMMIT();
    };
    issue(0);
    issue(1);

    int wid = tid >> 5, lane = tid & 31;
    int isU = wid >> 2;
    int rowblk = (wid & 3) * 32;
    int r4 = lane >> 2, qk = lane & 3;

    float acc[2][8][4];
#pragma unroll
    for (int mt = 0; mt < 2; mt++)
#pragma unroll
        for (int nt = 0; nt < 8; nt++)
#pragma unroll
            for (int i = 0; i < 4; i++) acc[mt][nt][i] = 0.0f;

    const int NC = HH / BK;   // 32
    for (int c = 0; c < NC; c++) {
        if (c < NC - 1) { CP_WAIT(1); } else { CP_WAIT(0); }
        __syncthreads();
        if (c + 2 < NC) issue((c + 2) % NS);

        const float* stg = dsm + (size_t)(c % NS) * STGW;
        const unsigned* uA = (const unsigned*)stg;
        const float4* bv = (const float4*)((const char*)stg + ASTG + isU * BHALF + lane * BLANE);

        unsigned af[2][4][4];
#pragma unroll
        for (int mt = 0; mt < 2; mt++) {
            int rb = (rowblk + mt * 16 + r4) * ROWF + qk;
#pragma unroll
            for (int ko = 0; ko < 4; ko++) {
                int p = rb + ko * 8;
                af[mt][ko][0] = uA[p];
                af[mt][ko][1] = uA[p + 8 * ROWF];
                af[mt][ko][2] = uA[p + 4];
                af[mt][ko][3] = uA[p + 8 * ROWF + 4];
            }
        }
#pragma unroll
        for (int grp = 0; grp < 2; grp++) {
            float4 b[4][2];
#pragma unroll
            for (int q = 0; q < 4; q++) {
                b[q][0] = bv[(grp * 4 + q) * 2];
                b[q][1] = bv[(grp * 4 + q) * 2 + 1];
            }
#pragma unroll
            for (int ko = 0; ko < 4; ko++) {
#pragma unroll
                for (int q = 0; q < 4; q++) {
                    int nt = grp * 4 + q;
                    float4 v = b[q][ko >> 1];
                    unsigned b0 = (ko & 1) ? __float_as_uint(v.z) : __float_as_uint(v.x);
                    unsigned b1 = (ko & 1) ? __float_as_uint(v.w) : __float_as_uint(v.y);
                    mma1688(acc[0][nt], af[0][ko], b0, b1);
                    mma1688(acc[1][nt], af[1][ko], b0, b1);
                }
            }
        }
    }
    __syncthreads();   // mma reads done before smem reuse

    // ---- epilogue: u-warps publish via smem; g-warps combine (tf32-rounded); store ----
    float* epf = dsm;   // 128 x 64, stride 66
    if (isU) {
#pragma unroll
        for (int mt = 0; mt < 2; mt++)
#pragma unroll
            for (int nt = 0; nt < 8; nt++)
#pragma unroll
                for (int i = 0; i < 4; i++) {
                    int row = rowblk + mt * 16 + r4 + ((i >> 1) ? 8 : 0);
                    int col = nt * 8 + qk * 2 + (i & 1);
                    epf[row * 66 + col] = acc[mt][nt][i];
                }
    }
    __syncthreads();
    if (!isU) {
#pragma unroll
        for (int mt = 0; mt < 2; mt++)
#pragma unroll
            for (int nt = 0; nt < 8; nt++)
#pragma unroll
                for (int i = 0; i < 4; i++) {
                    int row = rowblk + mt * 16 + r4 + ((i >> 1) ? 8 : 0);
                    int col = nt * 8 + qk * 2 + (i & 1);
                    float u = epf[row * 66 + col];
                    float g = acc[mt][nt][i];
                    float y = (g / (1.0f + expf(-g))) * u;
                    epf[row * 66 + col] = __uint_as_float(tf32r(y));
                }
    }
    __syncthreads();
    for (int idx = tid; idx < 128 * 64; idx += 256) {
        int rr = idx >> 6, cc = idx & 63;
        if (row0 + rr < n_e)
            g_act[(size_t)(base + row0 + rr) * FF + f0 + cc] = epf[rr * 66 + cc];
    }
}

// ======================= GEMM2: out += wt * (act @ w2^T) =======================
__global__ __launch_bounds__(256)
void gemm2_kernel(float* __restrict__ out) {
    extern __shared__ float dsm[];
    __shared__ int   s_tok[128];
    __shared__ float s_wt[128];

    int e    = blockIdx.z;
    int n_e  = g_counts[e];
    int row0 = blockIdx.y * 128;
    if (row0 >= n_e) return;
    int bh   = blockIdx.x;           // htile
    int h0   = bh * 128;
    int base = g_offsets[e];
    int tid  = threadIdx.x;

    if (tid < 128) {
        int r = row0 + tid;
        s_tok[tid] = (r < n_e) ? g_pair_token[base + r] : 0;
        s_wt[tid]  = (r < n_e) ? g_pair_w[base + r] : 0.0f;
    }
    __syncthreads();

    const char* srcA[4];
    const char* srcB[4];
    int dofA[4], dofB[4];
    const char* wb = (const char*)(g_w2c + (((size_t)e * 8 + bh) * 112) * 4096);
#pragma unroll
    for (int i = 0; i < 4; i++) {
        int idx = tid + 256 * i;
        int row = idx >> 3, c = idx & 7;
        long arow = (long)base + row0 + row;
        if (arow > NPAIR - 1) arow = NPAIR - 1;
        srcA[i] = (const char*)(g_act + (size_t)arow * FF) + c * 16;
        dofA[i] = row * ROWB + c * 16;
        int mat = idx >> 9, bl = (idx >> 4) & 31, o = idx & 15;
        srcB[i] = wb + idx * 16;
        dofB[i] = ASTG + mat * BHALF + bl * BLANE + o * 16;
    }
    uint32_t sb0 = smem_u32(dsm);
    auto issue = [&](int s) {
        uint32_t sg = sb0 + s * STG;
#pragma unroll
        for (int i = 0; i < 4; i++) { CP16(sg + dofA[i], srcA[i]); srcA[i] += 128; }
#pragma unroll
        for (int i = 0; i < 4; i++) { CP16(sg + dofB[i], srcB[i]); srcB[i] += 16384; }
        CP_COMMIT();
    };
    issue(0);
    issue(1);

    int wid = tid >> 5, lane = tid & 31;
    int rowblk = (wid & 3) * 32;
    int isHi = wid >> 2;             // B half (cols 0-63 / 64-127)
    int colblk = isHi * 64;
    int r4 = lane >> 2, qk = lane & 3;

    float acc[2][8][4];
#pragma unroll
    for (int mt = 0; mt < 2; mt++)
#pragma unroll
        for (int nt = 0; nt < 8; nt++)
#pragma unroll
            for (int i = 0; i < 4; i++) acc[mt][nt][i] = 0.0f;

    const int NC = FF / BK;   // 112
    for (int c = 0; c < NC; c++) {
        if (c < NC - 1) { CP_WAIT(1); } else { CP_WAIT(0); }
        __syncthreads();
        if (c + 2 < NC) issue((c + 2) % NS);

        const float* stg = dsm + (size_t)(c % NS) * STGW;
        const unsigned* uA = (const unsigned*)stg;
        const float4* bv = (const float4*)((const char*)stg + ASTG + isHi * BHALF + lane * BLANE);

        unsigned af[2][4][4];
#pragma unroll
        for (int mt = 0; mt < 2; mt++) {
            int rb = (rowblk + mt * 16 + r4) * ROWF + qk;
#pragma unroll
            for (int ko = 0; ko < 4; ko++) {
                int p = rb + ko * 8;
                af[mt][ko][0] = uA[p];
                af[mt][ko][1] = uA[p + 8 * ROWF];
                af[mt][ko][2] = uA[p + 4];
                af[mt][ko][3] = uA[p + 8 * ROWF + 4];
            }
        }
#pragma unroll
        for (int grp = 0; grp < 2; grp++) {
            float4 b[4][2];
#pragma unroll
            for (int q = 0; q < 4; q++) {
                b[q][0] = bv[(grp * 4 + q) * 2];
                b[q][1] = bv[(grp * 4 + q) * 2 + 1];
            }
#pragma unroll
            for (int ko = 0; ko < 4; ko++) {
#pragma unroll
                for (int q = 0; q < 4; q++) {
                    int nt = grp * 4 + q;
                    float4 v = b[q][ko >> 1];
                    unsigned b0 = (ko & 1) ? __float_as_uint(v.z) : __float_as_uint(v.x);
                    unsigned b1 = (ko & 1) ? __float_as_uint(v.w) : __float_as_uint(v.y);
                    mma1688(acc[0][nt], af[0][ko], b0, b1);
                    mma1688(acc[1][nt], af[1][ko], b0, b1);
                }
            }
        }
    }

    // ---- epilogue: weighted atomic combine (exactly 2 adds per out element) ----
#pragma unroll
    for (int mt = 0; mt < 2; mt++)
#pragma unroll
        for (int i2 = 0; i2 < 2; i2++) {
            int row = rowblk + mt * 16 + r4 + i2 * 8;
            if (row0 + row >= n_e) continue;
            float wt = s_wt[row];
            float* op = out + (size_t)s_tok[row] * HH + h0;
#pragma unroll
            for (int nt = 0; nt < 8; nt++) {
                int col = colblk + nt * 8 + qk * 2;
                atomicAdd(op + col,     acc[mt][nt][i2 * 2]     * wt);
                atomicAdd(op + col + 1, acc[mt][nt][i2 * 2 + 1] * wt);
            }
        }
}

// ---------------- launch ----------------
extern "C" void kernel_launch(void* const* d_in, const int* in_sizes, int n_in,
                              void* d_out, int out_size) {
    (void)in_sizes; (void)n_in; (void)out_size;
    const float* x  = (const float*)d_in[0];
    const float* gw = (const float*)d_in[1];
    const float* w1 = (const float*)d_in[2];
    const float* w3 = (const float*)d_in[3];
    const float* w2 = (const float*)d_in[4];
    float* out = (float*)d_out;

    cudaFuncSetAttribute(gemm1_kernel, cudaFuncAttributeMaxDynamicSharedMemorySize, SMEM_DYN);
    cudaFuncSetAttribute(gemm2_kernel, cudaFuncAttributeMaxDynamicSharedMemorySize, SMEM_DYN);

    zero_kernel<<<(TT * HH + 255) / 256, 256>>>(out, TT * HH);
    conv_x_kernel<<<(TT * HH + 255) / 256, 256>>>(x);
    conv_w13_kernel<<<dim3(32, 56, EE), 512>>>(w1, w3);
    conv_w2_kernel<<<dim3(112, 8, EE), 512>>>(w2);
    router_kernel<<<TT / 8, 256>>>(x, gw);
    build_kernel<<<1, 256>>>();

    dim3 g1(FF / 64, TT / 128, EE);    // (56,16,8); dead tiles early-exit
    gemm1_kernel<<<g1, 256, SMEM_DYN>>>();

    dim3 g2(HH / 128, TT / 128, EE);   // (8,16,8)
    gemm2_kernel<<<g2, 256, SMEM_DYN>>>(out);
}

// round 10
// speedup vs baseline: 1.5395x; 1.5395x over previous
#include <cuda_runtime.h>
#include <math.h>
#include <stdint.h>

// ---------------- problem constants ----------------
#define TT 2048
#define HH 1024
#define EE 8
#define FF 3584
#define TOPK 2
#define NPAIR (TT * TOPK)
#define BK 32               // K floats per chunk (=128B per row)
#define NS 3                // pipeline stages
#define ROWB 144            // smem row stride bytes (36 floats: 32 data + 4 pad)
#define ROWF 36
#define ASTG (128 * ROWB)   // 18432 B (A tile: 128 rows)
#define STG  (2 * ASTG)     // 36864 B (A + B per stage)
#define SMEM_DYN (NS * STG) // 110592 B ; x2 CTAs = 221184 <= 228KB/SM

// ---------------- device scratch (static; no allocation) ----------------
__device__ int   g_topk_idx[TT][TOPK];
__device__ float g_topk_w[TT][TOPK];
__device__ int   g_counts[EE];
__device__ int   g_offsets[EE];
__device__ int   g_pair_token[NPAIR];
__device__ float g_pair_w[NPAIR];
__device__ float g_xs[(size_t)TT * HH];       // x, tf32-pre-rounded
__device__ float g_act[(size_t)NPAIR * FF];   // activations, tf32-pre-rounded

// ---------------- helpers ----------------
__device__ __forceinline__ uint32_t smem_u32(const void* p) {
    uint32_t a;
    asm("{ .reg .u64 t; cvta.to.shared.u64 t, %1; cvt.u32.u64 %0, t; }" : "=r"(a) : "l"(p));
    return a;
}
#define CP16(dst_u32, src_ptr) \
    asm volatile("cp.async.cg.shared.global [%0], [%1], 16;" :: "r"(dst_u32), "l"(src_ptr) : "memory")
#define CP_COMMIT() asm volatile("cp.async.commit_group;" ::: "memory")
#define CP_WAIT(n)  asm volatile("cp.async.wait_group %0;" :: "n"(n) : "memory")

__device__ __forceinline__ unsigned tf32r(float v) {
    unsigned r;
    asm("cvt.rna.tf32.f32 %0, %1;" : "=r"(r) : "f"(v));
    return r;
}
// m16n8k8 tf32 mma, f32 accum
__device__ __forceinline__ void mma1688(float* c, const unsigned* a, unsigned b0, unsigned b1) {
    asm volatile(
        "mma.sync.aligned.m16n8k8.row.col.f32.tf32.tf32.f32 "
        "{%0,%1,%2,%3}, {%4,%5,%6,%7}, {%8,%9}, {%0,%1,%2,%3};"
        : "+f"(c[0]), "+f"(c[1]), "+f"(c[2]), "+f"(c[3])
        : "r"(a[0]), "r"(a[1]), "r"(a[2]), "r"(a[3]), "r"(b0), "r"(b1));
}

// ---------------- small kernels ----------------
__global__ void zero_kernel(float* __restrict__ out, int n) {
    int i = blockIdx.x * blockDim.x + threadIdx.x;
    if (i < n) out[i] = 0.0f;
}
__global__ void conv_x_kernel(const float* __restrict__ x) {
    int i = blockIdx.x * blockDim.x + threadIdx.x;
    if (i < TT * HH) g_xs[i] = __uint_as_float(tf32r(x[i]));
}
__global__ void router_kernel(const float* __restrict__ x, const float* __restrict__ gw) {
    int warp = (blockIdx.x * blockDim.x + threadIdx.x) >> 5;
    int lane = threadIdx.x & 31;
    if (warp >= TT) return;
    const float* xr = x + (size_t)warp * HH;
    float logit[EE];
#pragma unroll
    for (int e = 0; e < EE; e++) {
        const float* g = gw + (size_t)e * HH;
        float s = 0.0f;
        for (int i = lane; i < HH; i += 32) s += xr[i] * g[i];
#pragma unroll
        for (int o = 16; o > 0; o >>= 1) s += __shfl_xor_sync(0xffffffffu, s, o);
        logit[e] = s;
    }
    if (lane == 0) {
        int i0 = 0;
#pragma unroll
        for (int e = 1; e < EE; e++) if (logit[e] > logit[i0]) i0 = e;
        int i1 = (i0 == 0) ? 1 : 0;
#pragma unroll
        for (int e = 0; e < EE; e++) {
            if (e == i0) continue;
            if (logit[e] > logit[i1]) i1 = e;
        }
        float d = logit[i1] - logit[i0];
        float z = expf(d);
        float w0 = 1.0f / (1.0f + z);
        g_topk_idx[warp][0] = i0;
        g_topk_idx[warp][1] = i1;
        g_topk_w[warp][0] = w0;
        g_topk_w[warp][1] = z * w0;
    }
}
__global__ void build_kernel() {
    __shared__ int s_cnt[EE];
    __shared__ int s_cur[EE];
    int tid = threadIdx.x;
    if (tid < EE) s_cnt[tid] = 0;
    __syncthreads();
    for (int p = tid; p < NPAIR; p += blockDim.x)
        atomicAdd(&s_cnt[g_topk_idx[p >> 1][p & 1]], 1);
    __syncthreads();
    if (tid == 0) {
        int off = 0;
        for (int e = 0; e < EE; e++) {
            g_offsets[e] = off;
            g_counts[e]  = s_cnt[e];
            s_cur[e]     = off;
            off += s_cnt[e];
        }
    }
    __syncthreads();
    for (int p = tid; p < NPAIR; p += blockDim.x) {
        int t = p >> 1, k = p & 1;
        int e = g_topk_idx[t][k];
        int slot = atomicAdd(&s_cur[e], 1);
        g_pair_token[slot] = t;
        g_pair_w[slot]     = g_topk_w[t][k];
    }
}

// ======================= GEMM1: act = silu(x@w1^T) * (x@w3^T) =======================
// CTA 128 rows x 64 f-cols; warps 0-3 g (w1), warps 4-7 u (w3).
// 3-stage cp.async pipeline; A pre-rounded tf32 (no cvt), B cvt at frag load.
__global__ __launch_bounds__(256, 2)
void gemm1_kernel(const float* __restrict__ w1, const float* __restrict__ w3) {
    extern __shared__ float dsm[];
    __shared__ int s_tok[128];

    int e    = blockIdx.z;
    int n_e  = g_counts[e];
    int row0 = blockIdx.y * 128;
    if (row0 >= n_e) return;
    int f0   = blockIdx.x * 64;
    int base = g_offsets[e];
    int tid  = threadIdx.x;

    if (tid < 128) {
        int r = row0 + tid;
        s_tok[tid] = (r < n_e) ? g_pair_token[base + r] : 0;
    }
    __syncthreads();

    // cp.async descriptors: 4 A 16B-chunks + 4 B 16B-chunks per thread per k-chunk
    const char* srcA[4];
    const char* srcB[4];
    int dofA[4], dofB[4];
#pragma unroll
    for (int i = 0; i < 4; i++) {
        int idx = tid + 256 * i;
        int row = idx >> 3, c = idx & 7;
        srcA[i] = (const char*)(g_xs + (size_t)s_tok[row] * HH) + c * 16;
        const float* wb = (row < 64)
            ? w1 + ((size_t)e * FF + f0 + row) * HH
            : w3 + ((size_t)e * FF + f0 + row - 64) * HH;
        srcB[i] = (const char*)wb + c * 16;
        dofA[i] = row * ROWB + c * 16;
        dofB[i] = ASTG + row * ROWB + c * 16;
    }
    uint32_t sb0 = smem_u32(dsm);
    auto issue = [&](int s) {
        uint32_t sg = sb0 + s * STG;
#pragma unroll
        for (int i = 0; i < 4; i++) { CP16(sg + dofA[i], srcA[i]); srcA[i] += 128; }
#pragma unroll
        for (int i = 0; i < 4; i++) { CP16(sg + dofB[i], srcB[i]); srcB[i] += 128; }
        CP_COMMIT();
    };
    issue(0);
    issue(1);

    int wid = tid >> 5, lane = tid & 31;
    int isU = wid >> 2;
    int rowblk = (wid & 3) * 32;
    int r4 = lane >> 2, qk = lane & 3;

    float acc[2][8][4];
#pragma unroll
    for (int mt = 0; mt < 2; mt++)
#pragma unroll
        for (int nt = 0; nt < 8; nt++)
#pragma unroll
            for (int i = 0; i < 4; i++) acc[mt][nt][i] = 0.0f;

    const int NC = HH / BK;   // 32
    for (int c = 0; c < NC; c++) {
        if (c < NC - 1) { CP_WAIT(1); } else { CP_WAIT(0); }
        __syncthreads();
        if (c + 2 < NC) issue((c + 2) % NS);

        const float* stg = dsm + (size_t)(c % NS) * (STG / 4);
        const unsigned* sA = (const unsigned*)stg;
        const float* sB = stg + ASTG / 4 + (isU * 64) * ROWF;
#pragma unroll
        for (int ko = 0; ko < 4; ko++) {
            int kb = ko * 8 + qk;
            unsigned af[2][4];
#pragma unroll
            for (int mt = 0; mt < 2; mt++) {
                const unsigned* p = sA + (rowblk + mt * 16 + r4) * ROWF + kb;
                af[mt][0] = p[0];
                af[mt][1] = p[8 * ROWF];
                af[mt][2] = p[4];
                af[mt][3] = p[8 * ROWF + 4];
            }
#pragma unroll
            for (int nt = 0; nt < 8; nt++) {
                const float* q = sB + (nt * 8 + r4) * ROWF + kb;
                unsigned b0 = tf32r(q[0]);
                unsigned b1 = tf32r(q[4]);
                mma1688(acc[0][nt], af[0], b0, b1);
                mma1688(acc[1][nt], af[1], b0, b1);
            }
        }
    }
    __syncthreads();   // mma reads done before smem reuse

    // ---- epilogue: u-warps publish via smem; g-warps combine (tf32-rounded); store ----
    float* epf = dsm;   // 128 x 64, stride 66
    if (isU) {
#pragma unroll
        for (int mt = 0; mt < 2; mt++)
#pragma unroll
            for (int nt = 0; nt < 8; nt++)
#pragma unroll
                for (int i = 0; i < 4; i++) {
                    int row = rowblk + mt * 16 + r4 + ((i >> 1) ? 8 : 0);
                    int col = nt * 8 + qk * 2 + (i & 1);
                    epf[row * 66 + col] = acc[mt][nt][i];
                }
    }
    __syncthreads();
    if (!isU) {
#pragma unroll
        for (int mt = 0; mt < 2; mt++)
#pragma unroll
            for (int nt = 0; nt < 8; nt++)
#pragma unroll
                for (int i = 0; i < 4; i++) {
                    int row = rowblk + mt * 16 + r4 + ((i >> 1) ? 8 : 0);
                    int col = nt * 8 + qk * 2 + (i & 1);
                    float u = epf[row * 66 + col];
                    float g = acc[mt][nt][i];
                    float y = (g / (1.0f + expf(-g))) * u;
                    epf[row * 66 + col] = __uint_as_float(tf32r(y));
                }
    }
    __syncthreads();
    for (int idx = tid; idx < 128 * 64; idx += 256) {
        int rr = idx >> 6, cc = idx & 63;
        if (row0 + rr < n_e)
            g_act[(size_t)(base + row0 + rr) * FF + f0 + cc] = epf[rr * 66 + cc];
    }
}

// ======================= GEMM2: out += wt * (act @ w2^T) =======================
// CTA 128 rows x 128 h-cols; warps 4x2 (32x64 per warp).
__global__ __launch_bounds__(256, 2)
void gemm2_kernel(const float* __restrict__ w2, float* __restrict__ out) {
    extern __shared__ float dsm[];
    __shared__ int   s_tok[128];
    __shared__ float s_wt[128];

    int e    = blockIdx.z;
    int n_e  = g_counts[e];
    int row0 = blockIdx.y * 128;
    if (row0 >= n_e) return;
    int h0   = blockIdx.x * 128;
    int base = g_offsets[e];
    int tid  = threadIdx.x;

    if (tid < 128) {
        int r = row0 + tid;
        s_tok[tid] = (r < n_e) ? g_pair_token[base + r] : 0;
        s_wt[tid]  = (r < n_e) ? g_pair_w[base + r] : 0.0f;
    }
    __syncthreads();

    const char* srcA[4];
    const char* srcB[4];
    int dofA[4], dofB[4];
#pragma unroll
    for (int i = 0; i < 4; i++) {
        int idx = tid + 256 * i;
        int row = idx >> 3, c = idx & 7;
        long arow = (long)base + row0 + row;
        if (arow > NPAIR - 1) arow = NPAIR - 1;
        srcA[i] = (const char*)(g_act + (size_t)arow * FF) + c * 16;
        srcB[i] = (const char*)(w2 + ((size_t)e * HH + h0 + row) * FF) + c * 16;
        dofA[i] = row * ROWB + c * 16;
        dofB[i] = ASTG + row * ROWB + c * 16;
    }
    uint32_t sb0 = smem_u32(dsm);
    auto issue = [&](int s) {
        uint32_t sg = sb0 + s * STG;
#pragma unroll
        for (int i = 0; i < 4; i++) { CP16(sg + dofA[i], srcA[i]); srcA[i] += 128; }
#pragma unroll
        for (int i = 0; i < 4; i++) { CP16(sg + dofB[i], srcB[i]); srcB[i] += 128; }
        CP_COMMIT();
    };
    issue(0);
    issue(1);

    int wid = tid >> 5, lane = tid & 31;
    int rowblk = (wid & 3) * 32;
    int colblk = (wid >> 2) * 64;
    int r4 = lane >> 2, qk = lane & 3;

    float acc[2][8][4];
#pragma unroll
    for (int mt = 0; mt < 2; mt++)
#pragma unroll
        for (int nt = 0; nt < 8; nt++)
#pragma unroll
            for (int i = 0; i < 4; i++) acc[mt][nt][i] = 0.0f;

    const int NC = FF / BK;   // 112
    for (int c = 0; c < NC; c++) {
        if (c < NC - 1) { CP_WAIT(1); } else { CP_WAIT(0); }
        __syncthreads();
        if (c + 2 < NC) issue((c + 2) % NS);

        const float* stg = dsm + (size_t)(c % NS) * (STG / 4);
        const unsigned* sA = (const unsigned*)stg;
        const float* sB = stg + ASTG / 4 + colblk * ROWF;
#pragma unroll
        for (int ko = 0; ko < 4; ko++) {
            int kb = ko * 8 + qk;
            unsigned af[2][4];
#pragma unroll
            for (int mt = 0; mt < 2; mt++) {
                const unsigned* p = sA + (rowblk + mt * 16 + r4) * ROWF + kb;
                af[mt][0] = p[0];
                af[mt][1] = p[8 * ROWF];
                af[mt][2] = p[4];
                af[mt][3] = p[8 * ROWF + 4];
            }
#pragma unroll
            for (int nt = 0; nt < 8; nt++) {
                const float* q = sB + (nt * 8 + r4) * ROWF + kb;
                unsigned b0 = tf32r(q[0]);
                unsigned b1 = tf32r(q[4]);
                mma1688(acc[0][nt], af[0], b0, b1);
                mma1688(acc[1][nt], af[1], b0, b1);
            }
        }
    }

    // ---- epilogue: weighted atomic combine (exactly 2 adds per out element) ----
#pragma unroll
    for (int mt = 0; mt < 2; mt++)
#pragma unroll
        for (int i2 = 0; i2 < 2; i2++) {
            int row = rowblk + mt * 16 + r4 + i2 * 8;
            if (row0 + row >= n_e) continue;
            float wt = s_wt[row];
            float* op = out + (size_t)s_tok[row] * HH + h0;
#pragma unroll
            for (int nt = 0; nt < 8; nt++) {
                int col = colblk + nt * 8 + qk * 2;
                atomicAdd(op + col,     acc[mt][nt][i2 * 2]     * wt);
                atomicAdd(op + col + 1, acc[mt][nt][i2 * 2 + 1] * wt);
            }
        }
}

// ---------------- launch ----------------
extern "C" void kernel_launch(void* const* d_in, const int* in_sizes, int n_in,
                              void* d_out, int out_size) {
    (void)in_sizes; (void)n_in; (void)out_size;
    const float* x  = (const float*)d_in[0];
    const float* gw = (const float*)d_in[1];
    const float* w1 = (const float*)d_in[2];
    const float* w3 = (const float*)d_in[3];
    const float* w2 = (const float*)d_in[4];
    float* out = (float*)d_out;

    cudaFuncSetAttribute(gemm1_kernel, cudaFuncAttributeMaxDynamicSharedMemorySize, SMEM_DYN);
    cudaFuncSetAttribute(gemm2_kernel, cudaFuncAttributeMaxDynamicSharedMemorySize, SMEM_DYN);

    zero_kernel<<<(TT * HH + 255) / 256, 256>>>(out, TT * HH);
    conv_x_kernel<<<(TT * HH + 255) / 256, 256>>>(x);
    router_kernel<<<TT / 8, 256>>>(x, gw);
    build_kernel<<<1, 256>>>();

    dim3 g1(FF / 64, TT / 128, EE);    // (56,16,8); dead tiles early-exit
    gemm1_kernel<<<g1, 256, SMEM_DYN>>>(w1, w3);

    dim3 g2(HH / 128, TT / 128, EE);   // (8,16,8)
    gemm2_kernel<<<g2, 256, SMEM_DYN>>>(w2, out);
}

// round 12
// speedup vs baseline: 1.9316x; 1.2547x over previous
#include <cuda_runtime.h>
#include <cuda_fp16.h>
#include <math.h>
#include <stdint.h>

// ---------------- problem constants ----------------
#define TT 2048
#define HH 1024
#define EE 8
#define FF 3584
#define TOPK 2
#define NPAIR (TT * TOPK)
#define BK 32                  // K elems per chunk
#define AROWB 80               // f16 tile row: 64B data + 16B pad
#define AROWW 20               // row stride in 32-bit words
#define ASTG (128 * AROWB)     // 10240 B per A stage
#define NSA 3                  // A pipeline stages (cp.async)
#define BSTG (128 * AROWB)     // 10240 B per B stage (f16)
#define BBASE (NSA * ASTG)     // 30720
#define SMEM_DYN (NSA * ASTG + 2 * BSTG)   // 51200 B ; 2 CTAs/SM easily fits

// ---------------- device scratch (static; no allocation) ----------------
__device__ int    g_topk_idx[TT][TOPK];
__device__ float  g_topk_w[TT][TOPK];
__device__ int    g_counts[EE];
__device__ int    g_offsets[EE];
__device__ int    g_pair_token[NPAIR];
__device__ float  g_pair_w[NPAIR];
__device__ __half g_xs[(size_t)TT * HH];       // x, fp16 (rn)
__device__ __half g_act[(size_t)NPAIR * FF];   // activations, fp16 (rn)

// ---------------- helpers ----------------
__device__ __forceinline__ uint32_t smem_u32(const void* p) {
    uint32_t a;
    asm("{ .reg .u64 t; cvta.to.shared.u64 t, %1; cvt.u32.u64 %0, t; }" : "=r"(a) : "l"(p));
    return a;
}
#define CP16(dst_u32, src_ptr) \
    asm volatile("cp.async.cg.shared.global [%0], [%1], 16;" :: "r"(dst_u32), "l"(src_ptr) : "memory")
#define CP_COMMIT() asm volatile("cp.async.commit_group;" ::: "memory")
#define CP_WAIT(n)  asm volatile("cp.async.wait_group %0;" :: "n"(n) : "memory")

__device__ __forceinline__ unsigned h2pack(float lo, float hi) {
    __half2 h = __floats2half2_rn(lo, hi);   // .x (low 16) = lo
    return *(unsigned*)&h;
}
// m16n8k16 f16 mma, f32 accum
__device__ __forceinline__ void mmaf16(float* c, const unsigned* a, unsigned b0, unsigned b1) {
    asm volatile(
        "mma.sync.aligned.m16n8k16.row.col.f32.f16.f16.f32 "
        "{%0,%1,%2,%3}, {%4,%5,%6,%7}, {%8,%9}, {%0,%1,%2,%3};"
        : "+f"(c[0]), "+f"(c[1]), "+f"(c[2]), "+f"(c[3])
        : "r"(a[0]), "r"(a[1]), "r"(a[2]), "r"(a[3]), "r"(b0), "r"(b1));
}

// ---------------- small kernels ----------------
__global__ void zero_kernel(float* __restrict__ out, int n) {
    int i = blockIdx.x * blockDim.x + threadIdx.x;
    if (i < n) out[i] = 0.0f;
}
__global__ void conv_x_kernel(const float* __restrict__ x) {
    int i = blockIdx.x * blockDim.x + threadIdx.x;
    if (i < TT * HH) g_xs[i] = __float2half_rn(x[i]);
}
__global__ void router_kernel(const float* __restrict__ x, const float* __restrict__ gw) {
    int warp = (blockIdx.x * blockDim.x + threadIdx.x) >> 5;
    int lane = threadIdx.x & 31;
    if (warp >= TT) return;
    const float* xr = x + (size_t)warp * HH;
    float logit[EE];
#pragma unroll
    for (int e = 0; e < EE; e++) {
        const float* g = gw + (size_t)e * HH;
        float s = 0.0f;
        for (int i = lane; i < HH; i += 32) s += xr[i] * g[i];
#pragma unroll
        for (int o = 16; o > 0; o >>= 1) s += __shfl_xor_sync(0xffffffffu, s, o);
        logit[e] = s;
    }
    if (lane == 0) {
        int i0 = 0;
#pragma unroll
        for (int e = 1; e < EE; e++) if (logit[e] > logit[i0]) i0 = e;
        int i1 = (i0 == 0) ? 1 : 0;
#pragma unroll
        for (int e = 0; e < EE; e++) {
            if (e == i0) continue;
            if (logit[e] > logit[i1]) i1 = e;
        }
        float d = logit[i1] - logit[i0];
        float z = expf(d);
        float w0 = 1.0f / (1.0f + z);
        g_topk_idx[warp][0] = i0;
        g_topk_idx[warp][1] = i1;
        g_topk_w[warp][0] = w0;
        g_topk_w[warp][1] = z * w0;
    }
}
__global__ void build_kernel() {
    __shared__ int s_cnt[EE];
    __shared__ int s_cur[EE];
    int tid = threadIdx.x;
    if (tid < EE) s_cnt[tid] = 0;
    __syncthreads();
    for (int p = tid; p < NPAIR; p += blockDim.x)
        atomicAdd(&s_cnt[g_topk_idx[p >> 1][p & 1]], 1);
    __syncthreads();
    if (tid == 0) {
        int off = 0;
        for (int e = 0; e < EE; e++) {
            g_offsets[e] = off;
            g_counts[e]  = s_cnt[e];
            s_cur[e]     = off;
            off += s_cnt[e];
        }
    }
    __syncthreads();
    for (int p = tid; p < NPAIR; p += blockDim.x) {
        int t = p >> 1, k = p & 1;
        int e = g_topk_idx[t][k];
        int slot = atomicAdd(&s_cur[e], 1);
        g_pair_token[slot] = t;
        g_pair_w[slot]     = g_topk_w[t][k];
    }
}

// ======================= GEMM1: act = silu(x@w1^T) * (x@w3^T) =======================
// CTA 128 rows x 64 f-cols; warps 0-3 g (w1 rows 0-63 of B tile), warps 4-7 u (w3, rows 64-127).
// A: fp16 via cp.async (3 stages). B: fp32 LDG -> f16 STS (2 stages, 1-chunk reg prefetch).
__global__ __launch_bounds__(256, 2)
void gemm1_kernel(const float* __restrict__ w1, const float* __restrict__ w3) {
    extern __shared__ char dsm[];
    __shared__ int s_tok[128];

    int e    = blockIdx.z;
    int n_e  = g_counts[e];
    int row0 = blockIdx.y * 128;
    if (row0 >= n_e) return;
    int f0   = blockIdx.x * 64;
    int base = g_offsets[e];
    int tid  = threadIdx.x;

    if (tid < 128) {
        int r = row0 + tid;
        s_tok[tid] = (r < n_e) ? g_pair_token[base + r] : 0;
    }
    __syncthreads();

    // A cp.async: 2 x 16B chunks per thread per k-chunk
    const char* srcA[2];
    int dofA[2];
#pragma unroll
    for (int i = 0; i < 2; i++) {
        int idx = tid + 256 * i;
        int row = idx >> 2, c = idx & 3;
        srcA[i] = (const char*)(g_xs + (size_t)s_tok[row] * HH) + c * 16;
        dofA[i] = row * AROWB + c * 16;
    }
    uint32_t sb0 = smem_u32(dsm);
    auto issueA = [&](int s) {
        uint32_t sg = sb0 + s * ASTG;
#pragma unroll
        for (int i = 0; i < 2; i++) { CP16(sg + dofA[i], srcA[i]); srcA[i] += 64; }
        CP_COMMIT();
    };
    issueA(0);
    issueA(1);

    // B: fp32 source, 16 floats per thread per chunk
    int brow = tid >> 1, bhf = tid & 1;
    const float* bsrc = ((brow < 64)
        ? w1 + ((size_t)e * FF + f0 + brow) * HH
        : w3 + ((size_t)e * FF + f0 + brow - 64) * HH) + bhf * 16;
    int bw = brow * AROWW + bhf * 8;   // dest word base in B stage
    float4 pb[4];
    {
        const float4* p = (const float4*)bsrc;
        pb[0] = p[0]; pb[1] = p[1]; pb[2] = p[2]; pb[3] = p[3];
    }

    int wid = tid >> 5, lane = tid & 31;
    int isU = wid >> 2;
    int rowblk = (wid & 3) * 32;
    int r4 = lane >> 2, qk = lane & 3;

    float acc[2][8][4];
#pragma unroll
    for (int mt = 0; mt < 2; mt++)
#pragma unroll
        for (int nt = 0; nt < 8; nt++)
#pragma unroll
            for (int i = 0; i < 4; i++) acc[mt][nt][i] = 0.0f;

    const int NC = HH / BK;   // 32
    for (int c = 0; c < NC; c++) {
        if (c < NC - 1) { CP_WAIT(1); } else { CP_WAIT(0); }
        // STS B chunk c (converted to f16) into stage c&1
        {
            unsigned us[8];
#pragma unroll
            for (int i = 0; i < 4; i++) {
                us[2 * i]     = h2pack(pb[i].x, pb[i].y);
                us[2 * i + 1] = h2pack(pb[i].z, pb[i].w);
            }
            unsigned* bst = (unsigned*)(dsm + BBASE + (c & 1) * BSTG);
            *(uint4*)(bst + bw)     = make_uint4(us[0], us[1], us[2], us[3]);
            *(uint4*)(bst + bw + 4) = make_uint4(us[4], us[5], us[6], us[7]);
        }
        __syncthreads();
        if (c + 2 < NC) issueA((c + 2) % NSA);
        if (c + 1 < NC) {
            const float4* p = (const float4*)(bsrc + (c + 1) * BK);
            pb[0] = p[0]; pb[1] = p[1]; pb[2] = p[2]; pb[3] = p[3];
        }
        const unsigned* sA = (const unsigned*)(dsm + (c % NSA) * ASTG);
        const unsigned* sB = (const unsigned*)(dsm + BBASE + (c & 1) * BSTG) + isU * 64 * AROWW;
#pragma unroll
        for (int ko2 = 0; ko2 < 2; ko2++) {
            unsigned af[2][4];
#pragma unroll
            for (int mt = 0; mt < 2; mt++) {
                int ab = (rowblk + mt * 16 + r4) * AROWW + ko2 * 8 + qk;
                af[mt][0] = sA[ab];
                af[mt][1] = sA[ab + 8 * AROWW];
                af[mt][2] = sA[ab + 4];
                af[mt][3] = sA[ab + 8 * AROWW + 4];
            }
#pragma unroll
            for (int nt = 0; nt < 8; nt++) {
                int bb = (nt * 8 + r4) * AROWW + ko2 * 8 + qk;
                unsigned b0 = sB[bb];
                unsigned b1 = sB[bb + 4];
                mmaf16(acc[0][nt], af[0], b0, b1);
                mmaf16(acc[1][nt], af[1], b0, b1);
            }
        }
    }
    __syncthreads();   // all mma reads done before smem reuse

    // ---- epilogue: u-warps publish via smem; g-warps combine; store f16 ----
    float* epf = (float*)dsm;   // 128 x 64, stride 66 (33792 B < 51200)
    if (isU) {
#pragma unroll
        for (int mt = 0; mt < 2; mt++)
#pragma unroll
            for (int nt = 0; nt < 8; nt++)
#pragma unroll
                for (int i = 0; i < 4; i++) {
                    int row = rowblk + mt * 16 + r4 + ((i >> 1) ? 8 : 0);
                    int col = nt * 8 + qk * 2 + (i & 1);
                    epf[row * 66 + col] = acc[mt][nt][i];
                }
    }
    __syncthreads();
    if (!isU) {
#pragma unroll
        for (int mt = 0; mt < 2; mt++)
#pragma unroll
            for (int nt = 0; nt < 8; nt++)
#pragma unroll
                for (int i = 0; i < 4; i++) {
                    int row = rowblk + mt * 16 + r4 + ((i >> 1) ? 8 : 0);
                    int col = nt * 8 + qk * 2 + (i & 1);
                    float u = epf[row * 66 + col];
                    float g = acc[mt][nt][i];
                    epf[row * 66 + col] = (g / (1.0f + expf(-g))) * u;
                }
    }
    __syncthreads();
    for (int idx = tid; idx < 128 * 64; idx += 256) {
        int rr = idx >> 6, cc = idx & 63;
        if (row0 + rr < n_e)
            g_act[(size_t)(base + row0 + rr) * FF + f0 + cc] = __float2half_rn(epf[rr * 66 + cc]);
    }
}

// ======================= GEMM2: out += wt * (act @ w2^T) =======================
// CTA 128 rows x 128 h-cols; warps 4x2 (32x64 per warp). Same pipeline.
__global__ __launch_bounds__(256, 2)
void gemm2_kernel(const float* __restrict__ w2, float* __restrict__ out) {
    extern __shared__ char dsm[];
    __shared__ int   s_tok[128];
    __shared__ float s_wt[128];

    int e    = blockIdx.z;
    int n_e  = g_counts[e];
    int row0 = blockIdx.y * 128;
    if (row0 >= n_e) return;
    int h0   = blockIdx.x * 128;
    int base = g_offsets[e];
    int tid  = threadIdx.x;

    if (tid < 128) {
        int r = row0 + tid;
        s_tok[tid] = (r < n_e) ? g_pair_token[base + r] : 0;
        s_wt[tid]  = (r < n_e) ? g_pair_w[base + r] : 0.0f;
    }
    __syncthreads();

    const char* srcA[2];
    int dofA[2];
#pragma unroll
    for (int i = 0; i < 2; i++) {
        int idx = tid + 256 * i;
        int row = idx >> 2, c = idx & 3;
        long arow = (long)base + row0 + row;
        if (arow > NPAIR - 1) arow = NPAIR - 1;
        srcA[i] = (const char*)(g_act + (size_t)arow * FF) + c * 16;
        dofA[i] = row * AROWB + c * 16;
    }
    uint32_t sb0 = smem_u32(dsm);
    auto issueA = [&](int s) {
        uint32_t sg = sb0 + s * ASTG;
#pragma unroll
        for (int i = 0; i < 2; i++) { CP16(sg + dofA[i], srcA[i]); srcA[i] += 64; }
        CP_COMMIT();
    };
    issueA(0);
    issueA(1);

    int brow = tid >> 1, bhf = tid & 1;
    const float* bsrc = w2 + ((size_t)e * HH + h0 + brow) * FF + bhf * 16;
    int bw = brow * AROWW + bhf * 8;
    float4 pb[4];
    {
        const float4* p = (const float4*)bsrc;
        pb[0] = p[0]; pb[1] = p[1]; pb[2] = p[2]; pb[3] = p[3];
    }

    int wid = tid >> 5, lane = tid & 31;
    int rowblk = (wid & 3) * 32;
    int colblk = (wid >> 2) * 64;
    int r4 = lane >> 2, qk = lane & 3;

    float acc[2][8][4];
#pragma unroll
    for (int mt = 0; mt < 2; mt++)
#pragma unroll
        for (int nt = 0; nt < 8; nt++)
#pragma unroll
            for (int i = 0; i < 4; i++) acc[mt][nt][i] = 0.0f;

    const int NC = FF / BK;   // 112
    for (int c = 0; c < NC; c++) {
        if (c < NC - 1) { CP_WAIT(1); } else { CP_WAIT(0); }
        {
            unsigned us[8];
#pragma unroll
            for (int i = 0; i < 4; i++) {
                us[2 * i]     = h2pack(pb[i].x, pb[i].y);
                us[2 * i + 1] = h2pack(pb[i].z, pb[i].w);
            }
            unsigned* bst = (unsigned*)(dsm + BBASE + (c & 1) * BSTG);
            *(uint4*)(bst + bw)     = make_uint4(us[0], us[1], us[2], us[3]);
            *(uint4*)(bst + bw + 4) = make_uint4(us[4], us[5], us[6], us[7]);
        }
        __syncthreads();
        if (c + 2 < NC) issueA((c + 2) % NSA);
        if (c + 1 < NC) {
            const float4* p = (const float4*)(bsrc + (c + 1) * BK);
            pb[0] = p[0]; pb[1] = p[1]; pb[2] = p[2]; pb[3] = p[3];
        }
        const unsigned* sA = (const unsigned*)(dsm + (c % NSA) * ASTG);
        const unsigned* sB = (const unsigned*)(dsm + BBASE + (c & 1) * BSTG) + colblk * AROWW;
#pragma unroll
        for (int ko2 = 0; ko2 < 2; ko2++) {
            unsigned af[2][4];
#pragma unroll
            for (int mt = 0; mt < 2; mt++) {
                int ab = (rowblk + mt * 16 + r4) * AROWW + ko2 * 8 + qk;
                af[mt][0] = sA[ab];
                af[mt][1] = sA[ab + 8 * AROWW];
                af[mt][2] = sA[ab + 4];
                af[mt][3] = sA[ab + 8 * AROWW + 4];
            }
#pragma unroll
            for (int nt = 0; nt < 8; nt++) {
                int bb = (nt * 8 + r4) * AROWW + ko2 * 8 + qk;
                unsigned b0 = sB[bb];
                unsigned b1 = sB[bb + 4];
                mmaf16(acc[0][nt], af[0], b0, b1);
                mmaf16(acc[1][nt], af[1], b0, b1);
            }
        }
    }

    // ---- epilogue: weighted atomic combine (exactly 2 adds per out element) ----
#pragma unroll
    for (int mt = 0; mt < 2; mt++)
#pragma unroll
        for (int i2 = 0; i2 < 2; i2++) {
            int row = rowblk + mt * 16 + r4 + i2 * 8;
            if (row0 + row >= n_e) continue;
            float wt = s_wt[row];
            float* op = out + (size_t)s_tok[row] * HH + h0;
#pragma unroll
            for (int nt = 0; nt < 8; nt++) {
                int col = colblk + nt * 8 + qk * 2;
                atomicAdd(op + col,     acc[mt][nt][i2 * 2]     * wt);
                atomicAdd(op + col + 1, acc[mt][nt][i2 * 2 + 1] * wt);
            }
        }
}

// ---------------- launch ----------------
extern "C" void kernel_launch(void* const* d_in, const int* in_sizes, int n_in,
                              void* d_out, int out_size) {
    (void)in_sizes; (void)n_in; (void)out_size;
    const float* x  = (const float*)d_in[0];
    const float* gw = (const float*)d_in[1];
    const float* w1 = (const float*)d_in[2];
    const float* w3 = (const float*)d_in[3];
    const float* w2 = (const float*)d_in[4];
    float* out = (float*)d_out;

    cudaFuncSetAttribute(gemm1_kernel, cudaFuncAttributeMaxDynamicSharedMemorySize, SMEM_DYN);
    cudaFuncSetAttribute(gemm2_kernel, cudaFuncAttributeMaxDynamicSharedMemorySize, SMEM_DYN);

    zero_kernel<<<(TT * HH + 255) / 256, 256>>>(out, TT * HH);
    conv_x_kernel<<<(TT * HH + 255) / 256, 256>>>(x);
    router_kernel<<<TT / 8, 256>>>(x, gw);
    build_kernel<<<1, 256>>>();

    dim3 g1(FF / 64, TT / 128, EE);    // (56,16,8); dead tiles early-exit
    gemm1_kernel<<<g1, 256, SMEM_DYN>>>(w1, w3);

    dim3 g2(HH / 128, TT / 128, EE);   // (8,16,8)
    gemm2_kernel<<<g2, 256, SMEM_DYN>>>(w2, out);
}

// round 13
// speedup vs baseline: 2.4676x; 1.2775x over previous
#include <cuda_runtime.h>
#include <cuda_fp16.h>
#include <math.h>
#include <stdint.h>

// ---------------- problem constants ----------------
#define TT 2048
#define HH 1024
#define EE 8
#define FF 3584
#define TOPK 2
#define NPAIR (TT * TOPK)
#define BK 64               // K halfs per chunk (=128B per row)
#define NS 3                // pipeline stages
#define ROWB 144            // smem row stride bytes (128B data + 16B pad)
#define ROWW 36             // row stride in 32-bit words
#define ASTG (128 * ROWB)   // 18432 B per operand tile
#define STG  (2 * ASTG)     // 36864 B per stage (A + B)
#define SMEM_DYN (NS * STG) // 110592 B ; x2 CTAs/SM = 221184

// ---------------- device scratch (static; no allocation) ----------------
__device__ int    g_topk_idx[TT][TOPK];
__device__ float  g_topk_w[TT][TOPK];
__device__ int    g_counts[EE];
__device__ int    g_offsets[EE];
__device__ int    g_pair_token[NPAIR];
__device__ float  g_pair_w[NPAIR];
__device__ __half g_xs[(size_t)TT * HH];        // x, fp16 (rn)
__device__ __half g_act[(size_t)NPAIR * FF];    // activations, fp16 (rn)
__device__ __half g_w1h[(size_t)EE * FF * HH];  // weights, fp16 (rn), converted per launch
__device__ __half g_w3h[(size_t)EE * FF * HH];
__device__ __half g_w2h[(size_t)EE * HH * FF];

// ---------------- helpers ----------------
__device__ __forceinline__ uint32_t smem_u32(const void* p) {
    uint32_t a;
    asm("{ .reg .u64 t; cvta.to.shared.u64 t, %1; cvt.u32.u64 %0, t; }" : "=r"(a) : "l"(p));
    return a;
}
#define CP16(dst_u32, src_ptr) \
    asm volatile("cp.async.cg.shared.global [%0], [%1], 16;" :: "r"(dst_u32), "l"(src_ptr) : "memory")
#define CP_COMMIT() asm volatile("cp.async.commit_group;" ::: "memory")
#define CP_WAIT(n)  asm volatile("cp.async.wait_group %0;" :: "n"(n) : "memory")

__device__ __forceinline__ unsigned h2pack(float lo, float hi) {
    __half2 h = __floats2half2_rn(lo, hi);
    return *(unsigned*)&h;
}
// m16n8k16 f16 mma, f32 accum
__device__ __forceinline__ void mmaf16(float* c, const unsigned* a, unsigned b0, unsigned b1) {
    asm volatile(
        "mma.sync.aligned.m16n8k16.row.col.f32.f16.f16.f32 "
        "{%0,%1,%2,%3}, {%4,%5,%6,%7}, {%8,%9}, {%0,%1,%2,%3};"
        : "+f"(c[0]), "+f"(c[1]), "+f"(c[2]), "+f"(c[3])
        : "r"(a[0]), "r"(a[1]), "r"(a[2]), "r"(a[3]), "r"(b0), "r"(b1));
}

// ---------------- small kernels ----------------
__global__ void zero_kernel(float* __restrict__ out, int n) {
    int i = blockIdx.x * blockDim.x + threadIdx.x;
    if (i < n) out[i] = 0.0f;
}
__global__ void conv_x_kernel(const float* __restrict__ x) {
    int i = blockIdx.x * blockDim.x + threadIdx.x;
    if (i < TT * HH) g_xs[i] = __float2half_rn(x[i]);
}
// coalesced fp32 -> fp16 weight conversion: 8 elems/thread (uint4 in x2, uint4 out)
__global__ void conv_w_kernel(const float* __restrict__ src, __half* __restrict__ dst, int n8) {
    int i = blockIdx.x * blockDim.x + threadIdx.x;
    if (i >= n8) return;
    const float4* s = (const float4*)src + 2 * (size_t)i;
    float4 a = s[0], b = s[1];
    uint4 o;
    o.x = h2pack(a.x, a.y);
    o.y = h2pack(a.z, a.w);
    o.z = h2pack(b.x, b.y);
    o.w = h2pack(b.z, b.w);
    ((uint4*)dst)[i] = o;
}
__global__ void router_kernel(const float* __restrict__ x, const float* __restrict__ gw) {
    int warp = (blockIdx.x * blockDim.x + threadIdx.x) >> 5;
    int lane = threadIdx.x & 31;
    if (warp >= TT) return;
    const float* xr = x + (size_t)warp * HH;
    float logit[EE];
#pragma unroll
    for (int e = 0; e < EE; e++) {
        const float* g = gw + (size_t)e * HH;
        float s = 0.0f;
        for (int i = lane; i < HH; i += 32) s += xr[i] * g[i];
#pragma unroll
        for (int o = 16; o > 0; o >>= 1) s += __shfl_xor_sync(0xffffffffu, s, o);
        logit[e] = s;
    }
    if (lane == 0) {
        int i0 = 0;
#pragma unroll
        for (int e = 1; e < EE; e++) if (logit[e] > logit[i0]) i0 = e;
        int i1 = (i0 == 0) ? 1 : 0;
#pragma unroll
        for (int e = 0; e < EE; e++) {
            if (e == i0) continue;
            if (logit[e] > logit[i1]) i1 = e;
        }
        float d = logit[i1] - logit[i0];
        float z = expf(d);
        float w0 = 1.0f / (1.0f + z);
        g_topk_idx[warp][0] = i0;
        g_topk_idx[warp][1] = i1;
        g_topk_w[warp][0] = w0;
        g_topk_w[warp][1] = z * w0;
    }
}
__global__ void build_kernel() {
    __shared__ int s_cnt[EE];
    __shared__ int s_cur[EE];
    int tid = threadIdx.x;
    if (tid < EE) s_cnt[tid] = 0;
    __syncthreads();
    for (int p = tid; p < NPAIR; p += blockDim.x)
        atomicAdd(&s_cnt[g_topk_idx[p >> 1][p & 1]], 1);
    __syncthreads();
    if (tid == 0) {
        int off = 0;
        for (int e = 0; e < EE; e++) {
            g_offsets[e] = off;
            g_counts[e]  = s_cnt[e];
            s_cur[e]     = off;
            off += s_cnt[e];
        }
    }
    __syncthreads();
    for (int p = tid; p < NPAIR; p += blockDim.x) {
        int t = p >> 1, k = p & 1;
        int e = g_topk_idx[t][k];
        int slot = atomicAdd(&s_cur[e], 1);
        g_pair_token[slot] = t;
        g_pair_w[slot]     = g_topk_w[t][k];
    }
}

// ======================= GEMM1: act = silu(x@w1^T) * (x@w3^T) =======================
// CTA 128 rows x 64 f-cols; warps 0-3 g (w1 = B rows 0-63), warps 4-7 u (w3 = B rows 64-127).
// Both operands fp16 via 3-stage cp.async; BK=64; hot loop is LDS+mma only.
__global__ __launch_bounds__(256, 2)
void gemm1_kernel() {
    extern __shared__ char dsm[];
    __shared__ int s_tok[128];

    int e    = blockIdx.z;
    int n_e  = g_counts[e];
    int row0 = blockIdx.y * 128;
    if (row0 >= n_e) return;
    int f0   = blockIdx.x * 64;
    int base = g_offsets[e];
    int tid  = threadIdx.x;

    if (tid < 128) {
        int r = row0 + tid;
        s_tok[tid] = (r < n_e) ? g_pair_token[base + r] : 0;
    }
    __syncthreads();

    // cp.async descriptors: 4 A + 4 B 16B-chunks per thread per k-chunk
    const char* srcA[4];
    const char* srcB[4];
    int dofA[4], dofB[4];
#pragma unroll
    for (int i = 0; i < 4; i++) {
        int idx = tid + 256 * i;
        int row = idx >> 3, c = idx & 7;
        srcA[i] = (const char*)(g_xs + (size_t)s_tok[row] * HH) + c * 16;
        const __half* wb = (row < 64)
            ? g_w1h + ((size_t)e * FF + f0 + row) * HH
            : g_w3h + ((size_t)e * FF + f0 + row - 64) * HH;
        srcB[i] = (const char*)wb + c * 16;
        dofA[i] = row * ROWB + c * 16;
        dofB[i] = ASTG + row * ROWB + c * 16;
    }
    uint32_t sb0 = smem_u32(dsm);
    auto issue = [&](int s) {
        uint32_t sg = sb0 + s * STG;
#pragma unroll
        for (int i = 0; i < 4; i++) { CP16(sg + dofA[i], srcA[i]); srcA[i] += 128; }
#pragma unroll
        for (int i = 0; i < 4; i++) { CP16(sg + dofB[i], srcB[i]); srcB[i] += 128; }
        CP_COMMIT();
    };
    issue(0);
    issue(1);

    int wid = tid >> 5, lane = tid & 31;
    int isU = wid >> 2;
    int rowblk = (wid & 3) * 32;
    int r4 = lane >> 2, qk = lane & 3;

    float acc[2][8][4];
#pragma unroll
    for (int mt = 0; mt < 2; mt++)
#pragma unroll
        for (int nt = 0; nt < 8; nt++)
#pragma unroll
            for (int i = 0; i < 4; i++) acc[mt][nt][i] = 0.0f;

    const int NC = HH / BK;   // 16
    for (int c = 0; c < NC; c++) {
        if (c < NC - 1) { CP_WAIT(1); } else { CP_WAIT(0); }
        __syncthreads();
        if (c + 2 < NC) issue((c + 2) % NS);

        const unsigned* sA = (const unsigned*)(dsm + (c % NS) * STG);
        const unsigned* sB = (const unsigned*)(dsm + (c % NS) * STG + ASTG) + isU * 64 * ROWW;
#pragma unroll
        for (int ko = 0; ko < 4; ko++) {
            int kb = ko * 8 + qk;
            unsigned af[2][4];
#pragma unroll
            for (int mt = 0; mt < 2; mt++) {
                const unsigned* p = sA + (rowblk + mt * 16 + r4) * ROWW + kb;
                af[mt][0] = p[0];
                af[mt][1] = p[8 * ROWW];
                af[mt][2] = p[4];
                af[mt][3] = p[8 * ROWW + 4];
            }
#pragma unroll
            for (int nt = 0; nt < 8; nt++) {
                const unsigned* q = sB + (nt * 8 + r4) * ROWW + kb;
                unsigned b0 = q[0];
                unsigned b1 = q[4];
                mmaf16(acc[0][nt], af[0], b0, b1);
                mmaf16(acc[1][nt], af[1], b0, b1);
            }
        }
    }
    __syncthreads();   // all mma reads done before smem reuse

    // ---- epilogue: u-warps publish via smem; g-warps combine; store f16 ----
    float* epf = (float*)dsm;   // 128 x 64, stride 66
    if (isU) {
#pragma unroll
        for (int mt = 0; mt < 2; mt++)
#pragma unroll
            for (int nt = 0; nt < 8; nt++)
#pragma unroll
                for (int i = 0; i < 4; i++) {
                    int row = rowblk + mt * 16 + r4 + ((i >> 1) ? 8 : 0);
                    int col = nt * 8 + qk * 2 + (i & 1);
                    epf[row * 66 + col] = acc[mt][nt][i];
                }
    }
    __syncthreads();
    if (!isU) {
#pragma unroll
        for (int mt = 0; mt < 2; mt++)
#pragma unroll
            for (int nt = 0; nt < 8; nt++)
#pragma unroll
                for (int i = 0; i < 4; i++) {
                    int row = rowblk + mt * 16 + r4 + ((i >> 1) ? 8 : 0);
                    int col = nt * 8 + qk * 2 + (i & 1);
                    float u = epf[row * 66 + col];
                    float g = acc[mt][nt][i];
                    epf[row * 66 + col] = (g / (1.0f + expf(-g))) * u;
                }
    }
    __syncthreads();
    for (int idx = tid; idx < 128 * 64; idx += 256) {
        int rr = idx >> 6, cc = idx & 63;
        if (row0 + rr < n_e)
            g_act[(size_t)(base + row0 + rr) * FF + f0 + cc] = __float2half_rn(epf[rr * 66 + cc]);
    }
}

// ======================= GEMM2: out += wt * (act @ w2^T) =======================
// CTA 128 rows x 128 h-cols; warps 4x2 (32x64 per warp). Same pipeline.
__global__ __launch_bounds__(256, 2)
void gemm2_kernel(float* __restrict__ out) {
    extern __shared__ char dsm[];
    __shared__ int   s_tok[128];
    __shared__ float s_wt[128];

    int e    = blockIdx.z;
    int n_e  = g_counts[e];
    int row0 = blockIdx.y * 128;
    if (row0 >= n_e) return;
    int h0   = blockIdx.x * 128;
    int base = g_offsets[e];
    int tid  = threadIdx.x;

    if (tid < 128) {
        int r = row0 + tid;
        s_tok[tid] = (r < n_e) ? g_pair_token[base + r] : 0;
        s_wt[tid]  = (r < n_e) ? g_pair_w[base + r] : 0.0f;
    }
    __syncthreads();

    const char* srcA[4];
    const char* srcB[4];
    int dofA[4], dofB[4];
#pragma unroll
    for (int i = 0; i < 4; i++) {
        int idx = tid + 256 * i;
        int row = idx >> 3, c = idx & 7;
        long arow = (long)base + row0 + row;
        if (arow > NPAIR - 1) arow = NPAIR - 1;
        srcA[i] = (const char*)(g_act + (size_t)arow * FF) + c * 16;
        srcB[i] = (const char*)(g_w2h + ((size_t)e * HH + h0 + row) * FF) + c * 16;
        dofA[i] = row * ROWB + c * 16;
        dofB[i] = ASTG + row * ROWB + c * 16;
    }
    uint32_t sb0 = smem_u32(dsm);
    auto issue = [&](int s) {
        uint32_t sg = sb0 + s * STG;
#pragma unroll
        for (int i = 0; i < 4; i++) { CP16(sg + dofA[i], srcA[i]); srcA[i] += 128; }
#pragma unroll
        for (int i = 0; i < 4; i++) { CP16(sg + dofB[i], srcB[i]); srcB[i] += 128; }
        CP_COMMIT();
    };
    issue(0);
    issue(1);

    int wid = tid >> 5, lane = tid & 31;
    int rowblk = (wid & 3) * 32;
    int colblk = (wid >> 2) * 64;
    int r4 = lane >> 2, qk = lane & 3;

    float acc[2][8][4];
#pragma unroll
    for (int mt = 0; mt < 2; mt++)
#pragma unroll
        for (int nt = 0; nt < 8; nt++)
#pragma unroll
            for (int i = 0; i < 4; i++) acc[mt][nt][i] = 0.0f;

    const int NC = FF / BK;   // 56
    for (int c = 0; c < NC; c++) {
        if (c < NC - 1) { CP_WAIT(1); } else { CP_WAIT(0); }
        __syncthreads();
        if (c + 2 < NC) issue((c + 2) % NS);

        const unsigned* sA = (const unsigned*)(dsm + (c % NS) * STG);
        const unsigned* sB = (const unsigned*)(dsm + (c % NS) * STG + ASTG) + colblk * ROWW;
#pragma unroll
        for (int ko = 0; ko < 4; ko++) {
            int kb = ko * 8 + qk;
            unsigned af[2][4];
#pragma unroll
            for (int mt = 0; mt < 2; mt++) {
                const unsigned* p = sA + (rowblk + mt * 16 + r4) * ROWW + kb;
                af[mt][0] = p[0];
                af[mt][1] = p[8 * ROWW];
                af[mt][2] = p[4];
                af[mt][3] = p[8 * ROWW + 4];
            }
#pragma unroll
            for (int nt = 0; nt < 8; nt++) {
                const unsigned* q = sB + (nt * 8 + r4) * ROWW + kb;
                unsigned b0 = q[0];
                unsigned b1 = q[4];
                mmaf16(acc[0][nt], af[0], b0, b1);
                mmaf16(acc[1][nt], af[1], b0, b1);
            }
        }
    }

    // ---- epilogue: weighted atomic combine (exactly 2 adds per out element) ----
#pragma unroll
    for (int mt = 0; mt < 2; mt++)
#pragma unroll
        for (int i2 = 0; i2 < 2; i2++) {
            int row = rowblk + mt * 16 + r4 + i2 * 8;
            if (row0 + row >= n_e) continue;
            float wt = s_wt[row];
            float* op = out + (size_t)s_tok[row] * HH + h0;
#pragma unroll
            for (int nt = 0; nt < 8; nt++) {
                int col = colblk + nt * 8 + qk * 2;
                atomicAdd(op + col,     acc[mt][nt][i2 * 2]     * wt);
                atomicAdd(op + col + 1, acc[mt][nt][i2 * 2 + 1] * wt);
            }
        }
}

// ---------------- launch ----------------
extern "C" void kernel_launch(void* const* d_in, const int* in_sizes, int n_in,
                              void* d_out, int out_size) {
    (void)in_sizes; (void)n_in; (void)out_size;
    const float* x  = (const float*)d_in[0];
    const float* gw = (const float*)d_in[1];
    const float* w1 = (const float*)d_in[2];
    const float* w3 = (const float*)d_in[3];
    const float* w2 = (const float*)d_in[4];
    float* out = (float*)d_out;

    cudaFuncSetAttribute(gemm1_kernel, cudaFuncAttributeMaxDynamicSharedMemorySize, SMEM_DYN);
    cudaFuncSetAttribute(gemm2_kernel, cudaFuncAttributeMaxDynamicSharedMemorySize, SMEM_DYN);

    // fetch device-symbol addresses (host side; graph-capture safe, no alloc)
    static __half* w1h_p = nullptr;
    static __half* w3h_p = nullptr;
    static __half* w2h_p = nullptr;
    if (!w1h_p) {
        cudaGetSymbolAddress((void**)&w1h_p, g_w1h);
        cudaGetSymbolAddress((void**)&w3h_p, g_w3h);
        cudaGetSymbolAddress((void**)&w2h_p, g_w2h);
    }

    const int NW13 = EE * FF * HH;   // 29360128
    const int NW2  = EE * HH * FF;

    zero_kernel<<<(TT * HH + 255) / 256, 256>>>(out, TT * HH);
    conv_x_kernel<<<(TT * HH + 255) / 256, 256>>>(x);
    conv_w_kernel<<<(NW13 / 8 + 255) / 256, 256>>>(w1, w1h_p, NW13 / 8);
    conv_w_kernel<<<(NW13 / 8 + 255) / 256, 256>>>(w3, w3h_p, NW13 / 8);
    conv_w_kernel<<<(NW2  / 8 + 255) / 256, 256>>>(w2, w2h_p, NW2  / 8);
    router_kernel<<<TT / 8, 256>>>(x, gw);
    build_kernel<<<1, 256>>>();

    dim3 g1(FF / 64, TT / 128, EE);    // (56,16,8); dead tiles early-exit
    gemm1_kernel<<<g1, 256, SMEM_DYN>>>();

    dim3 g2(HH / 128, TT / 128, EE);   // (8,16,8)
    gemm2_kernel<<<g2, 256, SMEM_DYN>>>(out);
}

// round 14
// speedup vs baseline: 2.5804x; 1.0457x over previous
#include <cuda_runtime.h>
#include <cuda_fp16.h>
#include <math.h>
#include <stdint.h>

// ---------------- problem constants ----------------
#define TT 2048
#define HH 1024
#define EE 8
#define FF 3584
#define TOPK 2
#define NPAIR (TT * TOPK)
#define BK 64               // K halfs per chunk (=128B per row)
#define NS 3                // pipeline stages
#define ROWB 144            // smem row stride bytes (128B data + 16B pad)
#define ROWW 36             // row stride in 32-bit words
#define ASTG (128 * ROWB)   // 18432 B per operand tile
#define STG  (2 * ASTG)     // 36864 B per stage (A + B)
#define SMEM_DYN (NS * STG) // 110592 B ; x2 CTAs/SM = 221184

// ---------------- device scratch (static; no allocation) ----------------
__device__ int    g_topk_idx[TT][TOPK];
__device__ float  g_topk_w[TT][TOPK];
__device__ int    g_counts[EE];
__device__ int    g_offsets[EE];
__device__ int    g_pair_token[NPAIR];
__device__ float  g_pair_w[NPAIR];
__device__ int    g_slot_of[NPAIR];             // (token,k) -> compacted slot
__device__ __half g_xs[(size_t)TT * HH];        // x, fp16 (rn)
__device__ __half g_act[(size_t)NPAIR * FF];    // activations, fp16 (rn)
__device__ __half g_w1h[(size_t)EE * FF * HH];  // fp16 weights (per-launch convert)
__device__ __half g_w3h[(size_t)EE * FF * HH];
__device__ __half g_w2h[(size_t)EE * HH * FF];
__device__ float  g_y[(size_t)NPAIR * HH];      // weighted per-slot gemm2 output

// ---------------- helpers ----------------
__device__ __forceinline__ uint32_t smem_u32(const void* p) {
    uint32_t a;
    asm("{ .reg .u64 t; cvta.to.shared.u64 t, %1; cvt.u32.u64 %0, t; }" : "=r"(a) : "l"(p));
    return a;
}
#define CP16(dst_u32, src_ptr) \
    asm volatile("cp.async.cg.shared.global [%0], [%1], 16;" :: "r"(dst_u32), "l"(src_ptr) : "memory")
#define CP_COMMIT() asm volatile("cp.async.commit_group;" ::: "memory")
#define CP_WAIT(n)  asm volatile("cp.async.wait_group %0;" :: "n"(n) : "memory")
#define LDMX4(r0, r1, r2, r3, addr) \
    asm volatile("ldmatrix.sync.aligned.m8n8.x4.shared.b16 {%0,%1,%2,%3}, [%4];" \
                 : "=r"(r0), "=r"(r1), "=r"(r2), "=r"(r3) : "r"(addr))

__device__ __forceinline__ unsigned h2pack(float lo, float hi) {
    __half2 h = __floats2half2_rn(lo, hi);
    return *(unsigned*)&h;
}
__device__ __forceinline__ void mmaf16(float* c, const unsigned* a, unsigned b0, unsigned b1) {
    asm volatile(
        "mma.sync.aligned.m16n8k16.row.col.f32.f16.f16.f32 "
        "{%0,%1,%2,%3}, {%4,%5,%6,%7}, {%8,%9}, {%0,%1,%2,%3};"
        : "+f"(c[0]), "+f"(c[1]), "+f"(c[2]), "+f"(c[3])
        : "r"(a[0]), "r"(a[1]), "r"(a[2]), "r"(a[3]), "r"(b0), "r"(b1));
}

// ---------------- small kernels ----------------
__global__ void conv_x_kernel(const float* __restrict__ x) {
    int i = blockIdx.x * blockDim.x + threadIdx.x;
    if (i < TT * HH) g_xs[i] = __float2half_rn(x[i]);
}
__global__ void conv_w_kernel(const float* __restrict__ src, __half* __restrict__ dst, int n8) {
    int i = blockIdx.x * blockDim.x + threadIdx.x;
    if (i >= n8) return;
    const float4* s = (const float4*)src + 2 * (size_t)i;
    float4 a = s[0], b = s[1];
    uint4 o;
    o.x = h2pack(a.x, a.y);
    o.y = h2pack(a.z, a.w);
    o.z = h2pack(b.x, b.y);
    o.w = h2pack(b.z, b.w);
    ((uint4*)dst)[i] = o;
}
__global__ void router_kernel(const float* __restrict__ x, const float* __restrict__ gw) {
    int warp = (blockIdx.x * blockDim.x + threadIdx.x) >> 5;
    int lane = threadIdx.x & 31;
    if (warp >= TT) return;
    const float* xr = x + (size_t)warp * HH;
    float logit[EE];
#pragma unroll
    for (int e = 0; e < EE; e++) {
        const float* g = gw + (size_t)e * HH;
        float s = 0.0f;
        for (int i = lane; i < HH; i += 32) s += xr[i] * g[i];
#pragma unroll
        for (int o = 16; o > 0; o >>= 1) s += __shfl_xor_sync(0xffffffffu, s, o);
        logit[e] = s;
    }
    if (lane == 0) {
        int i0 = 0;
#pragma unroll
        for (int e = 1; e < EE; e++) if (logit[e] > logit[i0]) i0 = e;
        int i1 = (i0 == 0) ? 1 : 0;
#pragma unroll
        for (int e = 0; e < EE; e++) {
            if (e == i0) continue;
            if (logit[e] > logit[i1]) i1 = e;
        }
        float d = logit[i1] - logit[i0];
        float z = expf(d);
        float w0 = 1.0f / (1.0f + z);
        g_topk_idx[warp][0] = i0;
        g_topk_idx[warp][1] = i1;
        g_topk_w[warp][0] = w0;
        g_topk_w[warp][1] = z * w0;
    }
}
__global__ void build_kernel() {
    __shared__ int s_cnt[EE];
    __shared__ int s_cur[EE];
    int tid = threadIdx.x;
    if (tid < EE) s_cnt[tid] = 0;
    __syncthreads();
    for (int p = tid; p < NPAIR; p += blockDim.x)
        atomicAdd(&s_cnt[g_topk_idx[p >> 1][p & 1]], 1);
    __syncthreads();
    if (tid == 0) {
        int off = 0;
        for (int e = 0; e < EE; e++) {
            g_offsets[e] = off;
            g_counts[e]  = s_cnt[e];
            s_cur[e]     = off;
            off += s_cnt[e];
        }
    }
    __syncthreads();
    for (int p = tid; p < NPAIR; p += blockDim.x) {
        int t = p >> 1, k = p & 1;
        int e = g_topk_idx[t][k];
        int slot = atomicAdd(&s_cur[e], 1);
        g_pair_token[slot] = t;
        g_pair_w[slot]     = g_topk_w[t][k];
        g_slot_of[p]       = slot;
    }
}
// out[t] = y[slot0] + y[slot1]  (weights already applied in gemm2)
__global__ void combine_kernel(float* __restrict__ out) {
    int i = blockIdx.x * blockDim.x + threadIdx.x;   // TT*HH/4 threads
    if (i >= TT * HH / 4) return;
    int t = i >> 8;              // HH/4 = 256 float4 per token
    int c = (i & 255) << 2;
    int s0 = g_slot_of[2 * t];
    int s1 = g_slot_of[2 * t + 1];
    float4 a = *(const float4*)(g_y + (size_t)s0 * HH + c);
    float4 b = *(const float4*)(g_y + (size_t)s1 * HH + c);
    float4 o = make_float4(a.x + b.x, a.y + b.y, a.z + b.z, a.w + b.w);
    *(float4*)(out + (size_t)t * HH + c) = o;
}

// ======================= GEMM1: act = silu(x@w1^T) * (x@w3^T) =======================
// CTA 128 rows x 64 f-cols; warps 0-3 g (w1 = B rows 0-63), warps 4-7 u (w3 = B rows 64-127).
// fp16 operands, 3-stage cp.async, ldmatrix fragment loads.
__global__ __launch_bounds__(256, 2)
void gemm1_kernel() {
    extern __shared__ char dsm[];
    __shared__ int s_tok[128];

    int e    = blockIdx.z;
    int n_e  = g_counts[e];
    int row0 = blockIdx.y * 128;
    if (row0 >= n_e) return;
    int f0   = blockIdx.x * 64;
    int base = g_offsets[e];
    int tid  = threadIdx.x;

    if (tid < 128) {
        int r = row0 + tid;
        s_tok[tid] = (r < n_e) ? g_pair_token[base + r] : 0;
    }
    __syncthreads();

    const char* srcA[4];
    const char* srcB[4];
    int dofA[4], dofB[4];
#pragma unroll
    for (int i = 0; i < 4; i++) {
        int idx = tid + 256 * i;
        int row = idx >> 3, c = idx & 7;
        srcA[i] = (const char*)(g_xs + (size_t)s_tok[row] * HH) + c * 16;
        const __half* wb = (row < 64)
            ? g_w1h + ((size_t)e * FF + f0 + row) * HH
            : g_w3h + ((size_t)e * FF + f0 + row - 64) * HH;
        srcB[i] = (const char*)wb + c * 16;
        dofA[i] = row * ROWB + c * 16;
        dofB[i] = ASTG + row * ROWB + c * 16;
    }
    uint32_t sb0 = smem_u32(dsm);
    auto issue = [&](int s) {
        uint32_t sg = sb0 + s * STG;
#pragma unroll
        for (int i = 0; i < 4; i++) { CP16(sg + dofA[i], srcA[i]); srcA[i] += 128; }
#pragma unroll
        for (int i = 0; i < 4; i++) { CP16(sg + dofB[i], srcB[i]); srcB[i] += 128; }
        CP_COMMIT();
    };
    issue(0);
    issue(1);

    int wid = tid >> 5, lane = tid & 31;
    int isU = wid >> 2;
    int rowblk = (wid & 3) * 32;
    int r4 = lane >> 2, qk = lane & 3;
    int lane15 = lane & 15, laneHi = lane >> 4;
    int lane7 = lane & 7, half16 = (lane >> 3) & 1;

    // ldmatrix per-lane address offsets (within stage)
    uint32_t aOff[2];
#pragma unroll
    for (int mt = 0; mt < 2; mt++)
        aOff[mt] = (rowblk + mt * 16 + lane15) * ROWB + laneHi * 16;
    uint32_t bOff[4];
#pragma unroll
    for (int pr = 0; pr < 4; pr++) {
        int ntsel = 2 * pr + (lane >> 4);           // lanes<16 -> nt=2pr, lanes>=16 -> 2pr+1
        bOff[pr] = ASTG + (isU * 64 + ntsel * 8 + lane7) * ROWB + half16 * 16;
    }

    float acc[2][8][4];
#pragma unroll
    for (int mt = 0; mt < 2; mt++)
#pragma unroll
        for (int nt = 0; nt < 8; nt++)
#pragma unroll
            for (int i = 0; i < 4; i++) acc[mt][nt][i] = 0.0f;

    const int NC = HH / BK;   // 16
    for (int c = 0; c < NC; c++) {
        if (c < NC - 1) { CP_WAIT(1); } else { CP_WAIT(0); }
        __syncthreads();
        if (c + 2 < NC) issue((c + 2) % NS);

        uint32_t sg = sb0 + (c % NS) * STG;
#pragma unroll
        for (int ko = 0; ko < 4; ko++) {
            unsigned af[2][4];
            LDMX4(af[0][0], af[0][1], af[0][2], af[0][3], sg + aOff[0] + ko * 32);
            LDMX4(af[1][0], af[1][1], af[1][2], af[1][3], sg + aOff[1] + ko * 32);
#pragma unroll
            for (int pr = 0; pr < 4; pr++) {
                unsigned b0a, b1a, b0b, b1b;
                LDMX4(b0a, b1a, b0b, b1b, sg + bOff[pr] + ko * 32);
                mmaf16(acc[0][2 * pr],     af[0], b0a, b1a);
                mmaf16(acc[1][2 * pr],     af[1], b0a, b1a);
                mmaf16(acc[0][2 * pr + 1], af[0], b0b, b1b);
                mmaf16(acc[1][2 * pr + 1], af[1], b0b, b1b);
            }
        }
    }
    __syncthreads();   // all mma reads done before smem reuse

    // ---- epilogue: u-warps publish via smem; g-warps combine; store f16 ----
    float* epf = (float*)dsm;   // 128 x 64, stride 66
    if (isU) {
#pragma unroll
        for (int mt = 0; mt < 2; mt++)
#pragma unroll
            for (int nt = 0; nt < 8; nt++)
#pragma unroll
                for (int i = 0; i < 4; i++) {
                    int row = rowblk + mt * 16 + r4 + ((i >> 1) ? 8 : 0);
                    int col = nt * 8 + qk * 2 + (i & 1);
                    epf[row * 66 + col] = acc[mt][nt][i];
                }
    }
    __syncthreads();
    if (!isU) {
#pragma unroll
        for (int mt = 0; mt < 2; mt++)
#pragma unroll
            for (int nt = 0; nt < 8; nt++)
#pragma unroll
                for (int i = 0; i < 4; i++) {
                    int row = rowblk + mt * 16 + r4 + ((i >> 1) ? 8 : 0);
                    int col = nt * 8 + qk * 2 + (i & 1);
                    float u = epf[row * 66 + col];
                    float g = acc[mt][nt][i];
                    epf[row * 66 + col] = (g / (1.0f + expf(-g))) * u;
                }
    }
    __syncthreads();
    for (int idx = tid; idx < 128 * 64; idx += 256) {
        int rr = idx >> 6, cc = idx & 63;
        if (row0 + rr < n_e)
            g_act[(size_t)(base + row0 + rr) * FF + f0 + cc] = __float2half_rn(epf[rr * 66 + cc]);
    }
}

// ======================= GEMM2: y[slot] = wt * (act @ w2^T) =======================
// CTA 128 rows x 128 h-cols; warps 4x2 (32x64 per warp). Non-atomic slot-buffer output.
__global__ __launch_bounds__(256, 2)
void gemm2_kernel() {
    extern __shared__ char dsm[];
    __shared__ float s_wt[128];

    int e    = blockIdx.z;
    int n_e  = g_counts[e];
    int row0 = blockIdx.y * 128;
    if (row0 >= n_e) return;
    int h0   = blockIdx.x * 128;
    int base = g_offsets[e];
    int tid  = threadIdx.x;

    if (tid < 128) {
        int r = row0 + tid;
        s_wt[tid] = (r < n_e) ? g_pair_w[base + r] : 0.0f;
    }
    __syncthreads();

    const char* srcA[4];
    const char* srcB[4];
    int dofA[4], dofB[4];
#pragma unroll
    for (int i = 0; i < 4; i++) {
        int idx = tid + 256 * i;
        int row = idx >> 3, c = idx & 7;
        long arow = (long)base + row0 + row;
        if (arow > NPAIR - 1) arow = NPAIR - 1;
        srcA[i] = (const char*)(g_act + (size_t)arow * FF) + c * 16;
        srcB[i] = (const char*)(g_w2h + ((size_t)e * HH + h0 + row) * FF) + c * 16;
        dofA[i] = row * ROWB + c * 16;
        dofB[i] = ASTG + row * ROWB + c * 16;
    }
    uint32_t sb0 = smem_u32(dsm);
    auto issue = [&](int s) {
        uint32_t sg = sb0 + s * STG;
#pragma unroll
        for (int i = 0; i < 4; i++) { CP16(sg + dofA[i], srcA[i]); srcA[i] += 128; }
#pragma unroll
        for (int i = 0; i < 4; i++) { CP16(sg + dofB[i], srcB[i]); srcB[i] += 128; }
        CP_COMMIT();
    };
    issue(0);
    issue(1);

    int wid = tid >> 5, lane = tid & 31;
    int rowblk = (wid & 3) * 32;
    int colblk = (wid >> 2) * 64;
    int r4 = lane >> 2, qk = lane & 3;
    int lane15 = lane & 15, laneHi = lane >> 4;
    int lane7 = lane & 7, half16 = (lane >> 3) & 1;

    uint32_t aOff[2];
#pragma unroll
    for (int mt = 0; mt < 2; mt++)
        aOff[mt] = (rowblk + mt * 16 + lane15) * ROWB + laneHi * 16;
    uint32_t bOff[4];
#pragma unroll
    for (int pr = 0; pr < 4; pr++) {
        int ntsel = 2 * pr + (lane >> 4);
        bOff[pr] = ASTG + (colblk + ntsel * 8 + lane7) * ROWB + half16 * 16;
    }

    float acc[2][8][4];
#pragma unroll
    for (int mt = 0; mt < 2; mt++)
#pragma unroll
        for (int nt = 0; nt < 8; nt++)
#pragma unroll
            for (int i = 0; i < 4; i++) acc[mt][nt][i] = 0.0f;

    const int NC = FF / BK;   // 56
    for (int c = 0; c < NC; c++) {
        if (c < NC - 1) { CP_WAIT(1); } else { CP_WAIT(0); }
        __syncthreads();
        if (c + 2 < NC) issue((c + 2) % NS);

        uint32_t sg = sb0 + (c % NS) * STG;
#pragma unroll
        for (int ko = 0; ko < 4; ko++) {
            unsigned af[2][4];
            LDMX4(af[0][0], af[0][1], af[0][2], af[0][3], sg + aOff[0] + ko * 32);
            LDMX4(af[1][0], af[1][1], af[1][2], af[1][3], sg + aOff[1] + ko * 32);
#pragma unroll
            for (int pr = 0; pr < 4; pr++) {
                unsigned b0a, b1a, b0b, b1b;
                LDMX4(b0a, b1a, b0b, b1b, sg + bOff[pr] + ko * 32);
                mmaf16(acc[0][2 * pr],     af[0], b0a, b1a);
                mmaf16(acc[1][2 * pr],     af[1], b0a, b1a);
                mmaf16(acc[0][2 * pr + 1], af[0], b0b, b1b);
                mmaf16(acc[1][2 * pr + 1], af[1], b0b, b1b);
            }
        }
    }

    // ---- epilogue: weighted non-atomic store to per-slot buffer ----
#pragma unroll
    for (int mt = 0; mt < 2; mt++)
#pragma unroll
        for (int i2 = 0; i2 < 2; i2++) {
            int row = rowblk + mt * 16 + r4 + i2 * 8;
            if (row0 + row >= n_e) continue;
            float wt = s_wt[row];
            float* yp = g_y + (size_t)(base + row0 + row) * HH + h0;
#pragma unroll
            for (int nt = 0; nt < 8; nt++) {
                int col = colblk + nt * 8 + qk * 2;
                float2 v = make_float2(acc[mt][nt][i2 * 2] * wt, acc[mt][nt][i2 * 2 + 1] * wt);
                *(float2*)(yp + col) = v;
            }
        }
}

// ---------------- launch ----------------
extern "C" void kernel_launch(void* const* d_in, const int* in_sizes, int n_in,
                              void* d_out, int out_size) {
    (void)in_sizes; (void)n_in; (void)out_size;
    const float* x  = (const float*)d_in[0];
    const float* gw = (const float*)d_in[1];
    const float* w1 = (const float*)d_in[2];
    const float* w3 = (const float*)d_in[3];
    const float* w2 = (const float*)d_in[4];
    float* out = (float*)d_out;

    cudaFuncSetAttribute(gemm1_kernel, cudaFuncAttributeMaxDynamicSharedMemorySize, SMEM_DYN);
    cudaFuncSetAttribute(gemm2_kernel, cudaFuncAttributeMaxDynamicSharedMemorySize, SMEM_DYN);

    static __half* w1h_p = nullptr;
    static __half* w3h_p = nullptr;
    static __half* w2h_p = nullptr;
    if (!w1h_p) {
        cudaGetSymbolAddress((void**)&w1h_p, g_w1h);
        cudaGetSymbolAddress((void**)&w3h_p, g_w3h);
        cudaGetSymbolAddress((void**)&w2h_p, g_w2h);
    }

    const int NW13 = EE * FF * HH;
    const int NW2  = EE * HH * FF;

    conv_x_kernel<<<(TT * HH + 255) / 256, 256>>>(x);
    conv_w_kernel<<<(NW13 / 8 + 255) / 256, 256>>>(w1, w1h_p, NW13 / 8);
    conv_w_kernel<<<(NW13 / 8 + 255) / 256, 256>>>(w3, w3h_p, NW13 / 8);
    conv_w_kernel<<<(NW2  / 8 + 255) / 256, 256>>>(w2, w2h_p, NW2  / 8);
    router_kernel<<<TT / 8, 256>>>(x, gw);
    build_kernel<<<1, 256>>>();

    dim3 g1(FF / 64, TT / 128, EE);    // (56,16,8); dead tiles early-exit
    gemm1_kernel<<<g1, 256, SMEM_DYN>>>();

    dim3 g2(HH / 128, TT / 128, EE);   // (8,16,8)
    gemm2_kernel<<<g2, 256, SMEM_DYN>>>();

    combine_kernel<<<(TT * HH / 4 + 255) / 256, 256>>>(out);
}

// round 15
// speedup vs baseline: 2.6229x; 1.0165x over previous
#include <cuda_runtime.h>
#include <cuda_fp16.h>
#include <math.h>
#include <stdint.h>

// ---------------- problem constants ----------------
#define TT 2048
#define HH 1024
#define EE 8
#define FF 3584
#define TOPK 2
#define NPAIR (TT * TOPK)
#define BK 64               // K halfs per chunk (=128B per row)
#define NS 3                // pipeline stages
#define ROWB 144            // smem row stride bytes (128B data + 16B pad)
#define ASTG (128 * ROWB)   // 18432 B per operand tile
#define STG  (2 * ASTG)     // 36864 B per stage (A + B)
#define SMEM_DYN (NS * STG) // 110592 B ; x2 CTAs/SM = 221184
#define MAXTILES 40

// ---------------- device scratch (static; no allocation) ----------------
__device__ int    g_topk_idx[TT][TOPK];
__device__ float  g_topk_w[TT][TOPK];
__device__ int    g_counts[EE];
__device__ int    g_offsets[EE];
__device__ int    g_pair_token[NPAIR];
__device__ float  g_pair_w[NPAIR];
__device__ int    g_slot_of[NPAIR];
__device__ int    g_ntiles;
__device__ int    g_tile_e[MAXTILES];
__device__ int    g_tile_row0[MAXTILES];
__device__ __half g_xs[(size_t)TT * HH];
__device__ __half g_act[(size_t)NPAIR * FF];
__device__ __half g_w1h[(size_t)EE * FF * HH];
__device__ __half g_w3h[(size_t)EE * FF * HH];
__device__ __half g_w2h[(size_t)EE * HH * FF];
__device__ float  g_y[(size_t)NPAIR * HH];

// ---------------- helpers ----------------
__device__ __forceinline__ uint32_t smem_u32(const void* p) {
    uint32_t a;
    asm("{ .reg .u64 t; cvta.to.shared.u64 t, %1; cvt.u32.u64 %0, t; }" : "=r"(a) : "l"(p));
    return a;
}
#define CP16(dst_u32, src_ptr) \
    asm volatile("cp.async.cg.shared.global [%0], [%1], 16;" :: "r"(dst_u32), "l"(src_ptr) : "memory")
#define CP_COMMIT() asm volatile("cp.async.commit_group;" ::: "memory")
#define CP_WAIT(n)  asm volatile("cp.async.wait_group %0;" :: "n"(n) : "memory")
#define LDMX4(r0, r1, r2, r3, addr) \
    asm volatile("ldmatrix.sync.aligned.m8n8.x4.shared.b16 {%0,%1,%2,%3}, [%4];" \
                 : "=r"(r0), "=r"(r1), "=r"(r2), "=r"(r3) : "r"(addr))

__device__ __forceinline__ unsigned h2pack(float lo, float hi) {
    __half2 h = __floats2half2_rn(lo, hi);
    return *(unsigned*)&h;
}
__device__ __forceinline__ void mmaf16(float* c, const unsigned* a, unsigned b0, unsigned b1) {
    asm volatile(
        "mma.sync.aligned.m16n8k16.row.col.f32.f16.f16.f32 "
        "{%0,%1,%2,%3}, {%4,%5,%6,%7}, {%8,%9}, {%0,%1,%2,%3};"
        : "+f"(c[0]), "+f"(c[1]), "+f"(c[2]), "+f"(c[3])
        : "r"(a[0]), "r"(a[1]), "r"(a[2]), "r"(a[3]), "r"(b0), "r"(b1));
}

// ---------------- small kernels ----------------
__global__ void conv_x_kernel(const float* __restrict__ x) {
    int i = blockIdx.x * blockDim.x + threadIdx.x;
    if (i < TT * HH) g_xs[i] = __float2half_rn(x[i]);
}
// single launch converting w1, w3, w2 (8 fp32 -> 8 fp16 per thread)
#define N8_13 (EE * FF * HH / 8)
#define N8_2  (EE * HH * FF / 8)
__global__ void conv_w_all_kernel(const float* __restrict__ w1,
                                  const float* __restrict__ w3,
                                  const float* __restrict__ w2) {
    int i = blockIdx.x * blockDim.x + threadIdx.x;
    const float* src;
    __half* dst;
    int j = i;
    if (j < N8_13)                { src = w1; dst = g_w1h; }
    else if ((j -= N8_13) < N8_13){ src = w3; dst = g_w3h; }
    else if ((j -= N8_13) < N8_2) { src = w2; dst = g_w2h; }
    else return;
    const float4* s = (const float4*)src + 2 * (size_t)j;
    float4 a = s[0], b = s[1];
    uint4 o;
    o.x = h2pack(a.x, a.y);
    o.y = h2pack(a.z, a.w);
    o.z = h2pack(b.x, b.y);
    o.w = h2pack(b.z, b.w);
    ((uint4*)dst)[j] = o;
}
__global__ void router_kernel(const float* __restrict__ x, const float* __restrict__ gw) {
    int warp = (blockIdx.x * blockDim.x + threadIdx.x) >> 5;
    int lane = threadIdx.x & 31;
    if (warp >= TT) return;
    const float* xr = x + (size_t)warp * HH;
    float logit[EE];
#pragma unroll
    for (int e = 0; e < EE; e++) {
        const float* g = gw + (size_t)e * HH;
        float s = 0.0f;
        for (int i = lane; i < HH; i += 32) s += xr[i] * g[i];
#pragma unroll
        for (int o = 16; o > 0; o >>= 1) s += __shfl_xor_sync(0xffffffffu, s, o);
        logit[e] = s;
    }
    if (lane == 0) {
        int i0 = 0;
#pragma unroll
        for (int e = 1; e < EE; e++) if (logit[e] > logit[i0]) i0 = e;
        int i1 = (i0 == 0) ? 1 : 0;
#pragma unroll
        for (int e = 0; e < EE; e++) {
            if (e == i0) continue;
            if (logit[e] > logit[i1]) i1 = e;
        }
        float d = logit[i1] - logit[i0];
        float z = expf(d);
        float w0 = 1.0f / (1.0f + z);
        g_topk_idx[warp][0] = i0;
        g_topk_idx[warp][1] = i1;
        g_topk_w[warp][0] = w0;
        g_topk_w[warp][1] = z * w0;
    }
}
__global__ void build_kernel() {
    __shared__ int s_cnt[EE];
    __shared__ int s_cur[EE];
    int tid = threadIdx.x;
    if (tid < EE) s_cnt[tid] = 0;
    __syncthreads();
    for (int p = tid; p < NPAIR; p += blockDim.x)
        atomicAdd(&s_cnt[g_topk_idx[p >> 1][p & 1]], 1);
    __syncthreads();
    if (tid == 0) {
        int off = 0, nt = 0;
        for (int e = 0; e < EE; e++) {
            g_offsets[e] = off;
            g_counts[e]  = s_cnt[e];
            s_cur[e]     = off;
            for (int r0 = 0; r0 < s_cnt[e]; r0 += 128) {
                g_tile_e[nt]    = e;
                g_tile_row0[nt] = r0;
                nt++;
            }
            off += s_cnt[e];
        }
        g_ntiles = nt;
    }
    __syncthreads();
    for (int p = tid; p < NPAIR; p += blockDim.x) {
        int t = p >> 1, k = p & 1;
        int e = g_topk_idx[t][k];
        int slot = atomicAdd(&s_cur[e], 1);
        g_pair_token[slot] = t;
        g_pair_w[slot]     = g_topk_w[t][k];
        g_slot_of[p]       = slot;
    }
}
__global__ void combine_kernel(float* __restrict__ out) {
    int i = blockIdx.x * blockDim.x + threadIdx.x;
    if (i >= TT * HH / 4) return;
    int t = i >> 8;
    int c = (i & 255) << 2;
    int s0 = g_slot_of[2 * t];
    int s1 = g_slot_of[2 * t + 1];
    float4 a = *(const float4*)(g_y + (size_t)s0 * HH + c);
    float4 b = *(const float4*)(g_y + (size_t)s1 * HH + c);
    *(float4*)(out + (size_t)t * HH + c) =
        make_float4(a.x + b.x, a.y + b.y, a.z + b.z, a.w + b.w);
}

// ======================= GEMM1: act = silu(x@w1^T) * (x@w3^T) =======================
__global__ __launch_bounds__(256, 2)
void gemm1_kernel() {
    extern __shared__ char dsm[];
    __shared__ int s_tok[128];

    int ti = blockIdx.y;
    if (ti >= g_ntiles) return;
    int e    = g_tile_e[ti];
    int row0 = g_tile_row0[ti];
    int n_e  = g_counts[e];
    int f0   = blockIdx.x * 64;
    int base = g_offsets[e];
    int tid  = threadIdx.x;

    if (tid < 128) {
        int r = row0 + tid;
        s_tok[tid] = (r < n_e) ? g_pair_token[base + r] : 0;
    }
    __syncthreads();

    const char* srcA[4];
    const char* srcB[4];
    int dofA[4], dofB[4];
#pragma unroll
    for (int i = 0; i < 4; i++) {
        int idx = tid + 256 * i;
        int row = idx >> 3, c = idx & 7;
        srcA[i] = (const char*)(g_xs + (size_t)s_tok[row] * HH) + c * 16;
        const __half* wb = (row < 64)
            ? g_w1h + ((size_t)e * FF + f0 + row) * HH
            : g_w3h + ((size_t)e * FF + f0 + row - 64) * HH;
        srcB[i] = (const char*)wb + c * 16;
        dofA[i] = row * ROWB + c * 16;
        dofB[i] = ASTG + row * ROWB + c * 16;
    }
    uint32_t sb0 = smem_u32(dsm);
    auto issue = [&](int s) {
        uint32_t sg = sb0 + s * STG;
#pragma unroll
        for (int i = 0; i < 4; i++) { CP16(sg + dofA[i], srcA[i]); srcA[i] += 128; }
#pragma unroll
        for (int i = 0; i < 4; i++) { CP16(sg + dofB[i], srcB[i]); srcB[i] += 128; }
        CP_COMMIT();
    };
    issue(0);
    issue(1);

    int wid = tid >> 5, lane = tid & 31;
    int isU = wid >> 2;
    int rowblk = (wid & 3) * 32;
    int r4 = lane >> 2, qk = lane & 3;
    int lane15 = lane & 15, laneHi = lane >> 4;
    int lane7 = lane & 7, half16 = (lane >> 3) & 1;

    uint32_t aOff[2];
#pragma unroll
    for (int mt = 0; mt < 2; mt++)
        aOff[mt] = (rowblk + mt * 16 + lane15) * ROWB + laneHi * 16;
    uint32_t bOff[4];
#pragma unroll
    for (int pr = 0; pr < 4; pr++) {
        int ntsel = 2 * pr + (lane >> 4);
        bOff[pr] = ASTG + (isU * 64 + ntsel * 8 + lane7) * ROWB + half16 * 16;
    }

    float acc[2][8][4];
#pragma unroll
    for (int mt = 0; mt < 2; mt++)
#pragma unroll
        for (int nt = 0; nt < 8; nt++)
#pragma unroll
            for (int i = 0; i < 4; i++) acc[mt][nt][i] = 0.0f;

    const int NC = HH / BK;   // 16
    for (int c = 0; c < NC; c++) {
        if (c < NC - 1) { CP_WAIT(1); } else { CP_WAIT(0); }
        __syncthreads();
        if (c + 2 < NC) issue((c + 2) % NS);

        uint32_t sg = sb0 + (c % NS) * STG;
#pragma unroll
        for (int ko = 0; ko < 4; ko++) {
            unsigned af[2][4];
            LDMX4(af[0][0], af[0][1], af[0][2], af[0][3], sg + aOff[0] + ko * 32);
            LDMX4(af[1][0], af[1][1], af[1][2], af[1][3], sg + aOff[1] + ko * 32);
            // software-pipelined B fragments across pr
            unsigned bc[4], bn[4];
            LDMX4(bc[0], bc[1], bc[2], bc[3], sg + bOff[0] + ko * 32);
#pragma unroll
            for (int pr = 0; pr < 4; pr++) {
                if (pr < 3) LDMX4(bn[0], bn[1], bn[2], bn[3], sg + bOff[pr + 1] + ko * 32);
                mmaf16(acc[0][2 * pr],     af[0], bc[0], bc[1]);
                mmaf16(acc[1][2 * pr],     af[1], bc[0], bc[1]);
                mmaf16(acc[0][2 * pr + 1], af[0], bc[2], bc[3]);
                mmaf16(acc[1][2 * pr + 1], af[1], bc[2], bc[3]);
#pragma unroll
                for (int q = 0; q < 4; q++) bc[q] = bn[q];
            }
        }
    }
    __syncthreads();

    // ---- epilogue ----
    float* epf = (float*)dsm;
    if (isU) {
#pragma unroll
        for (int mt = 0; mt < 2; mt++)
#pragma unroll
            for (int nt = 0; nt < 8; nt++)
#pragma unroll
                for (int i = 0; i < 4; i++) {
                    int row = rowblk + mt * 16 + r4 + ((i >> 1) ? 8 : 0);
                    int col = nt * 8 + qk * 2 + (i & 1);
                    epf[row * 66 + col] = acc[mt][nt][i];
                }
    }
    __syncthreads();
    if (!isU) {
#pragma unroll
        for (int mt = 0; mt < 2; mt++)
#pragma unroll
            for (int nt = 0; nt < 8; nt++)
#pragma unroll
                for (int i = 0; i < 4; i++) {
                    int row = rowblk + mt * 16 + r4 + ((i >> 1) ? 8 : 0);
                    int col = nt * 8 + qk * 2 + (i & 1);
                    float u = epf[row * 66 + col];
                    float g = acc[mt][nt][i];
                    epf[row * 66 + col] = (g / (1.0f + expf(-g))) * u;
                }
    }
    __syncthreads();
    for (int idx = tid; idx < 128 * 64; idx += 256) {
        int rr = idx >> 6, cc = idx & 63;
        if (row0 + rr < n_e)
            g_act[(size_t)(base + row0 + rr) * FF + f0 + cc] = __float2half_rn(epf[rr * 66 + cc]);
    }
}

// ======================= GEMM2: y[slot] = wt * (act @ w2^T) =======================
__global__ __launch_bounds__(256, 2)
void gemm2_kernel() {
    extern __shared__ char dsm[];
    __shared__ float s_wt[128];

    int ti = blockIdx.y;
    if (ti >= g_ntiles) return;
    int e    = g_tile_e[ti];
    int row0 = g_tile_row0[ti];
    int n_e  = g_counts[e];
    int h0   = blockIdx.x * 128;
    int base = g_offsets[e];
    int tid  = threadIdx.x;

    if (tid < 128) {
        int r = row0 + tid;
        s_wt[tid] = (r < n_e) ? g_pair_w[base + r] : 0.0f;
    }
    __syncthreads();

    const char* srcA[4];
    const char* srcB[4];
    int dofA[4], dofB[4];
#pragma unroll
    for (int i = 0; i < 4; i++) {
        int idx = tid + 256 * i;
        int row = idx >> 3, c = idx & 7;
        long arow = (long)base + row0 + row;
        if (arow > NPAIR - 1) arow = NPAIR - 1;
        srcA[i] = (const char*)(g_act + (size_t)arow * FF) + c * 16;
        srcB[i] = (const char*)(g_w2h + ((size_t)e * HH + h0 + row) * FF) + c * 16;
        dofA[i] = row * ROWB + c * 16;
        dofB[i] = ASTG + row * ROWB + c * 16;
    }
    uint32_t sb0 = smem_u32(dsm);
    auto issue = [&](int s) {
        uint32_t sg = sb0 + s * STG;
#pragma unroll
        for (int i = 0; i < 4; i++) { CP16(sg + dofA[i], srcA[i]); srcA[i] += 128; }
#pragma unroll
        for (int i = 0; i < 4; i++) { CP16(sg + dofB[i], srcB[i]); srcB[i] += 128; }
        CP_COMMIT();
    };
    issue(0);
    issue(1);

    int wid = tid >> 5, lane = tid & 31;
    int rowblk = (wid & 3) * 32;
    int colblk = (wid >> 2) * 64;
    int r4 = lane >> 2, qk = lane & 3;
    int lane15 = lane & 15, laneHi = lane >> 4;
    int lane7 = lane & 7, half16 = (lane >> 3) & 1;

    uint32_t aOff[2];
#pragma unroll
    for (int mt = 0; mt < 2; mt++)
        aOff[mt] = (rowblk + mt * 16 + lane15) * ROWB + laneHi * 16;
    uint32_t bOff[4];
#pragma unroll
    for (int pr = 0; pr < 4; pr++) {
        int ntsel = 2 * pr + (lane >> 4);
        bOff[pr] = ASTG + (colblk + ntsel * 8 + lane7) * ROWB + half16 * 16;
    }

    float acc[2][8][4];
#pragma unroll
    for (int mt = 0; mt < 2; mt++)
#pragma unroll
        for (int nt = 0; nt < 8; nt++)
#pragma unroll
            for (int i = 0; i < 4; i++) acc[mt][nt][i] = 0.0f;

    const int NC = FF / BK;   // 56
    for (int c = 0; c < NC; c++) {
        if (c < NC - 1) { CP_WAIT(1); } else { CP_WAIT(0); }
        __syncthreads();
        if (c + 2 < NC) issue((c + 2) % NS);

        uint32_t sg = sb0 + (c % NS) * STG;
#pragma unroll
        for (int ko = 0; ko < 4; ko++) {
            unsigned af[2][4];
            LDMX4(af[0][0], af[0][1], af[0][2], af[0][3], sg + aOff[0] + ko * 32);
            LDMX4(af[1][0], af[1][1], af[1][2], af[1][3], sg + aOff[1] + ko * 32);
            unsigned bc[4], bn[4];
            LDMX4(bc[0], bc[1], bc[2], bc[3], sg + bOff[0] + ko * 32);
#pragma unroll
            for (int pr = 0; pr < 4; pr++) {
                if (pr < 3) LDMX4(bn[0], bn[1], bn[2], bn[3], sg + bOff[pr + 1] + ko * 32);
                mmaf16(acc[0][2 * pr],     af[0], bc[0], bc[1]);
                mmaf16(acc[1][2 * pr],     af[1], bc[0], bc[1]);
                mmaf16(acc[0][2 * pr + 1], af[0], bc[2], bc[3]);
                mmaf16(acc[1][2 * pr + 1], af[1], bc[2], bc[3]);
#pragma unroll
                for (int q = 0; q < 4; q++) bc[q] = bn[q];
            }
        }
    }

    // ---- epilogue: weighted non-atomic store to per-slot buffer ----
#pragma unroll
    for (int mt = 0; mt < 2; mt++)
#pragma unroll
        for (int i2 = 0; i2 < 2; i2++) {
            int row = rowblk + mt * 16 + r4 + i2 * 8;
            if (row0 + row >= n_e) continue;
            float wt = s_wt[row];
            float* yp = g_y + (size_t)(base + row0 + row) * HH + h0;
#pragma unroll
            for (int nt = 0; nt < 8; nt++) {
                int col = colblk + nt * 8 + qk * 2;
                float2 v = make_float2(acc[mt][nt][i2 * 2] * wt, acc[mt][nt][i2 * 2 + 1] * wt);
                *(float2*)(yp + col) = v;
            }
        }
}

// ---------------- launch ----------------
extern "C" void kernel_launch(void* const* d_in, const int* in_sizes, int n_in,
                              void* d_out, int out_size) {
    (void)in_sizes; (void)n_in; (void)out_size;
    const float* x  = (const float*)d_in[0];
    const float* gw = (const float*)d_in[1];
    const float* w1 = (const float*)d_in[2];
    const float* w3 = (const float*)d_in[3];
    const float* w2 = (const float*)d_in[4];
    float* out = (float*)d_out;

    cudaFuncSetAttribute(gemm1_kernel, cudaFuncAttributeMaxDynamicSharedMemorySize, SMEM_DYN);
    cudaFuncSetAttribute(gemm2_kernel, cudaFuncAttributeMaxDynamicSharedMemorySize, SMEM_DYN);

    const int NCONV = 2 * N8_13 + N8_2;

    conv_x_kernel<<<(TT * HH + 255) / 256, 256>>>(x);
    conv_w_all_kernel<<<(NCONV + 255) / 256, 256>>>(w1, w3, w2);
    router_kernel<<<TT / 8, 256>>>(x, gw);
    build_kernel<<<1, 256>>>();

    dim3 g1(FF / 64, MAXTILES);    // (56, 40); inactive tiles early-exit
    gemm1_kernel<<<g1, 256, SMEM_DYN>>>();

    dim3 g2(HH / 128, MAXTILES);   // (8, 40)
    gemm2_kernel<<<g2, 256, SMEM_DYN>>>();

    combine_kernel<<<(TT * HH / 4 + 255) / 256, 256>>>(out);
}